// round 13
// baseline (speedup 1.0000x reference)
#include <cuda_runtime.h>
#include <math.h>
#include <stdint.h>

#define BB 64
#define NN 307
#define FF 64
#define TT 12
#define KK 3
#define CC 64
#define CT 64
#define FT (FF*TT)      // 768
#define CTT (CC*TT)     // 768
#define NNN (NN*NN)     // 94249
#define MM (BB*NN)      // 19648

#define SPRE_BLOCKS (154*3)     // 462
#define XT_BLOCKS   (39*KK*BB)  // 7488

// ---------------- scratch (static device globals; no allocs) ----------------
__device__ __align__(16) float g_xTheta[(size_t)KK*BB*NN*CTT];   // [k,b,i,t*64+c]
__device__ __align__(16) float g_sig[BB*NNN];
__device__ __align__(16) float g_S[BB*NNN];
__device__ __align__(16) float g_sg[(size_t)BB*NN*CTT];          // [b,j,t*64+c]
__device__ __align__(16) float g_VsT[NNN];
__device__ __align__(16) float g_E[BB*TT*TT];
__device__ __align__(16) float g_tlhs[BB*TT*FF];
__device__ __align__(16) float g_tlhs2[BB*TT*NN];
__device__ __align__(16) float g_trhs[BB*NN*TT];
__device__ __align__(16) float g_slhs[BB*NN*FF];
__device__ __align__(16) float g_slhs2[BB*NN*TT];
__device__ __align__(16) float g_srhsT[BB*NN*TT];               // [b,m,t] transposed

// ---------------- temporal attention ----------------
__global__ void k_tlhs(const float* __restrict__ x, const float* __restrict__ U1) {
    int b = blockIdx.x;
    int tid = threadIdx.x;                  // tid = f*12+t
    int f = tid / TT, t = tid % TT;
    const float* xb = x + (size_t)b*NN*FT;
    float acc = 0.f;
    for (int n = 0; n < NN; n++) acc += xb[n*FT + tid] * U1[n];
    g_tlhs[(b*TT + t)*FF + f] = acc;
}

__global__ void k_trhs(const float* __restrict__ x, const float* __restrict__ U3) {
    int idx = blockIdx.x*blockDim.x + threadIdx.x;
    if (idx >= BB*NN*TT) return;
    int t = idx % TT; int bn = idx / TT;
    const float* xr = x + (size_t)bn*FT + t;
    float acc = 0.f;
    #pragma unroll
    for (int f = 0; f < FF; f++) acc += xr[f*TT] * U3[f];
    g_trhs[idx] = acc;
}

__global__ void k_tlhs2(const float* __restrict__ U2) {
    int idx = blockIdx.x*blockDim.x + threadIdx.x;
    if (idx >= BB*TT*NN) return;
    int n = idx % NN; int bt = idx / NN;
    const float* l = g_tlhs + bt*FF;
    float acc = 0.f;
    #pragma unroll
    for (int f = 0; f < FF; f++) acc += l[f]*U2[f*NN + n];
    g_tlhs2[idx] = acc;
}

__global__ void k_tattn(const float* __restrict__ b_e, const float* __restrict__ V_e) {
    int b = blockIdx.x;
    int tid = threadIdx.x;
    __shared__ float sgm[144], Es[144], cmax[TT], csum[TT];
    if (tid < 144) {
        int u = tid / TT, s = tid % TT;
        const float* l = g_tlhs2 + (b*TT + u)*NN;
        const float* r = g_trhs + (size_t)b*NN*TT + s;
        float p = 0.f;
        for (int n = 0; n < NN; n++) p += l[n]*r[n*TT];
        sgm[tid] = 1.f/(1.f + expf(-(p + b_e[tid])));
    }
    __syncthreads();
    if (tid < 144) {
        int u = tid / TT, s = tid % TT;
        float e = 0.f;
        #pragma unroll
        for (int v = 0; v < TT; v++) e += V_e[u*TT+v]*sgm[v*TT+s];
        Es[tid] = e;
    }
    __syncthreads();
    if (tid < TT) {
        float m = -1e30f;
        for (int u = 0; u < TT; u++) m = fmaxf(m, Es[u*TT+tid]);
        float s = 0.f;
        for (int u = 0; u < TT; u++) s += expf(Es[u*TT+tid]-m);
        cmax[tid] = m; csum[tid] = s;
    }
    __syncthreads();
    if (tid < 144) {
        int s = tid % TT;
        g_E[b*144 + tid] = expf(Es[tid]-cmax[s])/csum[s];
    }
}

// fused: x_TAt row -> slhs (dot with W1) and srhsT (W3-weighted reduce over f).
__global__ void __launch_bounds__(256) k_xtat_fused(const float* __restrict__ x,
                                                    const float* __restrict__ W1,
                                                    const float* __restrict__ W3) {
    int b = blockIdx.y;
    __shared__ float Es[144];
    __shared__ float part[8][TT];
    if (threadIdx.x < 144) Es[threadIdx.x] = g_E[b*144 + threadIdx.x];
    __syncthreads();
    int row = blockIdx.x*256 + threadIdx.x;     // row = n*64 + f
    bool valid = row < NN*FF;
    float xv[TT];
    if (valid) {
        const float* xr = x + ((size_t)b*NN*FF + row)*TT;
        #pragma unroll
        for (int s = 0; s < TT; s++) xv[s] = xr[s];
    } else {
        #pragma unroll
        for (int s = 0; s < TT; s++) xv[s] = 0.f;
    }
    float o[TT];
    #pragma unroll
    for (int t = 0; t < TT; t++) {
        float a = 0.f;
        #pragma unroll
        for (int s = 0; s < TT; s++) a += xv[s]*Es[s*TT+t];
        o[t] = a;
    }
    if (valid) {
        float a = 0.f;
        #pragma unroll
        for (int t = 0; t < TT; t++) a += o[t]*W1[t];
        g_slhs[(size_t)b*NN*FF + row] = a;
    }
    int f = row & 63;
    float w = valid ? W3[f] : 0.f;
    float c[TT];
    #pragma unroll
    for (int t = 0; t < TT; t++) c[t] = w*o[t];
    #pragma unroll
    for (int off = 16; off > 0; off >>= 1) {
        #pragma unroll
        for (int t = 0; t < TT; t++)
            c[t] += __shfl_down_sync(0xffffffffu, c[t], off);
    }
    int warp = threadIdx.x >> 5, lane = threadIdx.x & 31;
    if (lane == 0) {
        #pragma unroll
        for (int t = 0; t < TT; t++) part[warp][t] = c[t];
    }
    __syncthreads();
    if ((warp & 1) == 0 && lane < TT) {
        int n = (blockIdx.x*256 + 32*warp) >> 6;
        if (n < NN)
            g_srhsT[((size_t)b*NN + n)*TT + lane] = part[warp][lane] + part[warp+1][lane];
    }
}

// ---------------- spatial attention ----------------
__global__ void k_slhs2(const float* __restrict__ W2) {
    int idx = blockIdx.x*blockDim.x + threadIdx.x;
    if (idx >= BB*NN*TT) return;
    int t = idx % TT; int bn = idx / TT;
    const float* l = g_slhs + bn*FF;
    float a = 0.f;
    #pragma unroll
    for (int f = 0; f < FF; f++) a += l[f]*W2[f*TT+t];
    g_slhs2[idx] = a;
}

__global__ void k_sprodsig(const float* __restrict__ b_s) {
    int idx = blockIdx.x*blockDim.x + threadIdx.x;
    if (idx >= BB*NN*NN) return;
    int m = idx % NN; int r = idx / NN; int n = r % NN; int b = r / NN;
    const float4* l4 = (const float4*)(g_slhs2 + ((size_t)b*NN + n)*TT);
    const float4* r4 = (const float4*)(g_srhsT + ((size_t)b*NN + m)*TT);
    float4 l0 = l4[0], l1 = l4[1], l2 = l4[2];
    float4 r0 = r4[0], r1 = r4[1], r2 = r4[2];
    float p = l0.x*r0.x + l0.y*r0.y + l0.z*r0.z + l0.w*r0.w
            + l1.x*r1.x + l1.y*r1.y + l1.z*r1.z + l1.w*r1.w
            + l2.x*r2.x + l2.y*r2.y + l2.z*r2.z + l2.w*r2.w;
    g_sig[idx] = 1.f/(1.f + __expf(-(p + b_s[n*NN + m])));
}

__global__ void k_vst(const float* __restrict__ V_s) {
    int idx = blockIdx.x*blockDim.x + threadIdx.x;
    if (idx >= NNN) return;
    int i = idx % NN, v = idx / NN;
    g_VsT[v*NN + i] = V_s[i*NN + v];
}

// ---------------- merged launch: spre blocks [0,462) + xtheta blocks -------
// spre:   S_pre[m, i] = sum_v sig[m, v]*VsT[v, i]  (identical to R6 k_spre)
// xtheta: xTheta[k,b,i,t,c] = sum_f x[b,i,f,t]*Theta[k,f,c]  (identical math)
__global__ void __launch_bounds__(256) k_sx(const float* __restrict__ x,
                                            const float* __restrict__ Theta) {
    __shared__ __align__(16) float As[2][8][132];
    __shared__ __align__(16) float Bs[2][8][128];
    __shared__ __align__(16) float th[64*64];
    __shared__ __align__(16) float xs2[64*96];
    const int blk = blockIdx.x;
    const int tid = threadIdx.x;
    if (blk < SPRE_BLOCKS) {
        const int m0 = (blk % 154) * 128;
        const int n0 = (blk / 154) * 128;
        const int tx = tid & 15, ty = tid >> 4;
        const int a_m = tid >> 1;
        const int a_v = (tid & 1) << 2;
        const int gm = m0 + a_m;
        float acc[8][8];
        #pragma unroll
        for (int r = 0; r < 8; r++)
            #pragma unroll
            for (int q = 0; q < 8; q++) acc[r][q] = 0.f;

        #pragma unroll
        for (int j = 0; j < 4; j++) {
            int v = a_v + j;
            As[0][a_v + j][a_m] = (gm < MM && v < NN) ? g_sig[(size_t)gm*NN + v] : 0.f;
        }
        #pragma unroll
        for (int p = 0; p < 4; p++) {
            int e = tid + p*256;
            int kk = e >> 7, il = e & 127;
            Bs[0][kk][il] = (kk < NN && n0+il < NN) ? g_VsT[kk*NN + n0 + il] : 0.f;
        }
        __syncthreads();
        const int NKT = 39;
        for (int kt = 0; kt < NKT; kt++) {
            int cur = kt & 1;
            float ar[4], br[4];
            if (kt + 1 < NKT) {
                int v0 = (kt+1)*8;
                #pragma unroll
                for (int j = 0; j < 4; j++) {
                    int v = v0 + a_v + j;
                    ar[j] = (gm < MM && v < NN) ? g_sig[(size_t)gm*NN + v] : 0.f;
                }
                #pragma unroll
                for (int p = 0; p < 4; p++) {
                    int e = tid + p*256;
                    int kk = e >> 7, il = e & 127;
                    int v = v0 + kk, i = n0 + il;
                    br[p] = (v < NN && i < NN) ? g_VsT[v*NN + i] : 0.f;
                }
            }
            #pragma unroll
            for (int kk = 0; kk < 8; kk++) {
                float4 a0 = *(const float4*)&As[cur][kk][ty*8];
                float4 a1 = *(const float4*)&As[cur][kk][ty*8+4];
                float4 b0 = *(const float4*)&Bs[cur][kk][tx*8];
                float4 b1 = *(const float4*)&Bs[cur][kk][tx*8+4];
                float av[8] = {a0.x,a0.y,a0.z,a0.w,a1.x,a1.y,a1.z,a1.w};
                float bv[8] = {b0.x,b0.y,b0.z,b0.w,b1.x,b1.y,b1.z,b1.w};
                #pragma unroll
                for (int r = 0; r < 8; r++)
                    #pragma unroll
                    for (int q = 0; q < 8; q++) acc[r][q] += av[r]*bv[q];
            }
            if (kt + 1 < NKT) {
                int nxt = cur ^ 1;
                #pragma unroll
                for (int j = 0; j < 4; j++) As[nxt][a_v + j][a_m] = ar[j];
                #pragma unroll
                for (int p = 0; p < 4; p++) {
                    int e = tid + p*256;
                    Bs[nxt][e>>7][e&127] = br[p];
                }
            }
            __syncthreads();
        }
        #pragma unroll
        for (int r = 0; r < 8; r++) {
            int m = m0 + ty*8 + r;
            if (m >= MM) continue;
            #pragma unroll
            for (int q = 0; q < 8; q++) {
                int i = n0 + tx*8 + q;
                if (i < NN) g_S[(size_t)m*NN + i] = acc[r][q];
            }
        }
    } else {
        const int e0 = blk - SPRE_BLOCKS;
        const int ig = e0 % 39;        // 0..38
        const int kb = e0 / 39;        // 0..191
        const int b = kb & 63, k = kb >> 6;
        const int i0 = ig * 8;
        for (int e = tid; e < 4096; e += 256) th[e] = Theta[k*4096 + e];
        for (int e = tid; e < 8*768; e += 256) {
            int ii = e / 768, r = e % 768;
            int f = r / 12, t = r % 12;
            float v = 0.f;
            if (i0 + ii < NN) v = x[(((size_t)(b*NN + i0 + ii))*64 + f)*12 + t];
            xs2[f*96 + t*8 + ii] = v;
        }
        __syncthreads();
        if (tid < 192) {
            const int cg = tid / 96;
            const int r2 = tid % 96;
            const int t = r2 >> 3, ii = r2 & 7;
            float acc[32];
            #pragma unroll
            for (int j = 0; j < 32; j++) acc[j] = 0.f;
            const float* xv = xs2 + t*8 + ii;
            const float* thc = th + cg*32;
            #pragma unroll 4
            for (int f = 0; f < 64; f++) {
                float xvf = xv[f*96];
                const float4* tp = (const float4*)(thc + f*64);
                #pragma unroll
                for (int j4 = 0; j4 < 8; j4++) {
                    float4 w = tp[j4];
                    acc[j4*4+0] += xvf*w.x; acc[j4*4+1] += xvf*w.y;
                    acc[j4*4+2] += xvf*w.z; acc[j4*4+3] += xvf*w.w;
                }
            }
            if (i0 + ii < NN) {
                float* o = &g_xTheta[(((size_t)(k*BB + b))*NN + i0 + ii)*768 + t*64 + cg*32];
                #pragma unroll
                for (int j4 = 0; j4 < 8; j4++)
                    ((float4*)o)[j4] = make_float4(acc[j4*4],acc[j4*4+1],acc[j4*4+2],acc[j4*4+3]);
            }
        }
    }
}

// softmax over rows a for each (b, col i)
__global__ void __launch_bounds__(64) k_softS() {
    int b = blockIdx.x;
    int i = blockIdx.y*64 + threadIdx.x;
    if (i >= NN) return;
    float* P = g_S + (size_t)b*NNN;
    float m = -1e30f;
    for (int a = 0; a < NN; a++) m = fmaxf(m, P[a*NN+i]);
    float s = 0.f;
    for (int a = 0; a < NN; a++) {
        float e = __expf(P[a*NN+i]-m);
        s += e;
        P[a*NN+i] = e;
    }
    float inv = 1.f/s;
    for (int a = 0; a < NN; a++) P[a*NN+i] *= inv;
}

// sg[b,j,tc] = relu( sum_k sum_i cheb[k,i,j]*S[b,i,j] * xTheta[k,b,i,tc] )
// 64x128x8 tiles, 8x8 micro, 128 threads, double buffered, k-loop fused. (R6)
__global__ void __launch_bounds__(128) k_cheb(const float* __restrict__ cheb) {
    __shared__ __align__(16) float As[2][8][64];
    __shared__ __align__(16) float Bs[2][8][128];
    const int b = blockIdx.y;
    const int m0 = (blockIdx.x / 6) * 64;
    const int n0 = (blockIdx.x % 6) * 128;
    const int tid = threadIdx.x;
    const int tx = tid & 15, ty = tid >> 4;   // ty 0..7
    const float* Sb = g_S + (size_t)b*NNN;
    float acc[8][8];
    #pragma unroll
    for (int r = 0; r < 8; r++)
        #pragma unroll
        for (int q = 0; q < 8; q++) acc[r][q] = 0.f;

    // prologue kt=0 (k=0, i0=0)
    #pragma unroll
    for (int p = 0; p < 4; p++) {
        int e = tid + p*128;
        int kk = e >> 6, jl = e & 63;
        int i = kk, j = m0 + jl;
        float av = 0.f;
        if (i < NN && j < NN) { int id = i*NN + j; av = cheb[id]*Sb[id]; }
        As[0][kk][jl] = av;
    }
    #pragma unroll
    for (int p = 0; p < 8; p++) {
        int e = tid + p*128;
        int kk = e >> 7, cl = e & 127;
        Bs[0][kk][cl] = (kk < NN) ? g_xTheta[((size_t)b*NN + kk)*CTT + n0 + cl] : 0.f;
    }
    __syncthreads();
    const int NKT = 3*39;  // 117
    for (int kt = 0; kt < NKT; kt++) {
        int cur = kt & 1;
        float ar[4], br[8];
        if (kt + 1 < NKT) {
            int kt1 = kt + 1;
            int kpoly = kt1 / 39;
            int i0 = (kt1 - kpoly*39) * 8;
            const float* Ck = cheb + kpoly*NNN;
            const float* Xk = g_xTheta + (size_t)(kpoly*BB + b)*NN*CTT;
            #pragma unroll
            for (int p = 0; p < 4; p++) {
                int e = tid + p*128;
                int kk = e >> 6, jl = e & 63;
                int i = i0 + kk, j = m0 + jl;
                float av = 0.f;
                if (i < NN && j < NN) { int id = i*NN + j; av = Ck[id]*Sb[id]; }
                ar[p] = av;
            }
            #pragma unroll
            for (int p = 0; p < 8; p++) {
                int e = tid + p*128;
                int kk = e >> 7, cl = e & 127;
                int i = i0 + kk;
                br[p] = (i < NN) ? Xk[(size_t)i*CTT + n0 + cl] : 0.f;
            }
        }
        #pragma unroll
        for (int kk = 0; kk < 8; kk++) {
            float4 a0 = *(const float4*)&As[cur][kk][ty*8];
            float4 a1 = *(const float4*)&As[cur][kk][ty*8+4];
            float4 b0 = *(const float4*)&Bs[cur][kk][tx*8];
            float4 b1 = *(const float4*)&Bs[cur][kk][tx*8+4];
            float av[8] = {a0.x,a0.y,a0.z,a0.w,a1.x,a1.y,a1.z,a1.w};
            float bv[8] = {b0.x,b0.y,b0.z,b0.w,b1.x,b1.y,b1.z,b1.w};
            #pragma unroll
            for (int r = 0; r < 8; r++)
                #pragma unroll
                for (int q = 0; q < 8; q++) acc[r][q] += av[r]*bv[q];
        }
        if (kt + 1 < NKT) {
            int nxt = cur ^ 1;
            #pragma unroll
            for (int p = 0; p < 4; p++) {
                int e = tid + p*128;
                As[nxt][e>>6][e&63] = ar[p];
            }
            #pragma unroll
            for (int p = 0; p < 8; p++) {
                int e = tid + p*128;
                Bs[nxt][e>>7][e&127] = br[p];
            }
        }
        __syncthreads();
    }
    float* o = g_sg + (size_t)b*NN*CTT;
    #pragma unroll
    for (int r = 0; r < 8; r++) {
        int j = m0 + ty*8 + r;
        if (j >= NN) continue;
        float* orow = o + (size_t)j*CTT + n0 + tx*8;
        float4 v0 = make_float4(fmaxf(acc[r][0],0.f), fmaxf(acc[r][1],0.f),
                                fmaxf(acc[r][2],0.f), fmaxf(acc[r][3],0.f));
        float4 v1 = make_float4(fmaxf(acc[r][4],0.f), fmaxf(acc[r][5],0.f),
                                fmaxf(acc[r][6],0.f), fmaxf(acc[r][7],0.f));
        ((float4*)orow)[0] = v0;
        ((float4*)orow)[1] = v1;
    }
}

// fused: rconv + tconv + relu + LayerNorm. Block = 4 bn, 256 threads. (R6)
__global__ void __launch_bounds__(256) k_epi(
    const float* __restrict__ x, const float* __restrict__ tw, const float* __restrict__ tb,
    const float* __restrict__ rw, const float* __restrict__ rb,
    const float* __restrict__ gamma, const float* __restrict__ beta, float* __restrict__ out)
{
    extern __shared__ __align__(16) float sh[];
    float* wT  = sh;                 // 64*193
    float* wR  = wT + 64*193;        // 64*65
    float* xs  = wR + 64*65;         // 4*768
    float* sgs = xs + 4*768;         // 4*1024
    float* hs  = sgs + 4*1024;       // 4*832
    float* smu = hs + 4*832;         // 48
    float* srs = smu + 48;           // 48
    const int tid = threadIdx.x;
    const int bn_l = tid >> 6;
    const int co = tid & 63;
    const int bn0 = blockIdx.x * 4;

    for (int e = tid; e < 64*192; e += 256) wT[(e/192)*193 + (e%192)] = tw[e];
    for (int e = tid; e < 64*64;  e += 256) wR[(e>>6)*65 + (e&63)] = rw[e];
    for (int e = tid; e < 4*768;  e += 256) xs[e] = x[(size_t)bn0*768 + e];
    for (int e = tid; e < 4*1024; e += 256) sgs[e] = 0.f;
    __syncthreads();
    for (int e = tid; e < 4*768; e += 256) {
        int bl = e / 768, r = e % 768, t = r >> 6, c = r & 63;
        sgs[bl*1024 + c*16 + t + 1] = g_sg[(size_t)(bn0+bl)*768 + r];
    }
    __syncthreads();

    float acc[12];
    {
        float bias = tb[co] + rb[co];
        #pragma unroll
        for (int t = 0; t < 12; t++) acc[t] = bias;
    }
    const float* xrow = xs + bn_l*768;
    const float* wr = wR + co*65;
    #pragma unroll 4
    for (int f = 0; f < 64; f++) {
        float wf = wr[f];
        float4 x0 = *(const float4*)&xrow[f*12];
        float4 x1 = *(const float4*)&xrow[f*12+4];
        float4 x2 = *(const float4*)&xrow[f*12+8];
        acc[0] += wf*x0.x; acc[1] += wf*x0.y; acc[2]  += wf*x0.z; acc[3]  += wf*x0.w;
        acc[4] += wf*x1.x; acc[5] += wf*x1.y; acc[6]  += wf*x1.z; acc[7]  += wf*x1.w;
        acc[8] += wf*x2.x; acc[9] += wf*x2.y; acc[10] += wf*x2.z; acc[11] += wf*x2.w;
    }
    const float* sgr = sgs + bn_l*1024;
    const float* wt = wT + co*193;
    #pragma unroll 2
    for (int c = 0; c < 64; c++) {
        float w0 = wt[c*3], w1 = wt[c*3+1], w2 = wt[c*3+2];
        float4 s0 = *(const float4*)&sgr[c*16];
        float4 s1 = *(const float4*)&sgr[c*16+4];
        float4 s2 = *(const float4*)&sgr[c*16+8];
        float4 s3 = *(const float4*)&sgr[c*16+12];
        float sv[14] = {s0.x,s0.y,s0.z,s0.w, s1.x,s1.y,s1.z,s1.w,
                        s2.x,s2.y,s2.z,s2.w, s3.x,s3.y};
        #pragma unroll
        for (int t = 0; t < 12; t++)
            acc[t] += sv[t]*w0 + sv[t+1]*w1 + sv[t+2]*w2;
    }
    #pragma unroll
    for (int t = 0; t < 12; t++) {
        acc[t] = fmaxf(acc[t], 0.f);
        hs[bn_l*832 + co*13 + t] = acc[t];
    }
    __syncthreads();
    if (tid < 48) {
        int bl = tid / 12, t = tid % 12;
        const float* h = hs + bl*832;
        float m = 0.f;
        for (int q = 0; q < 64; q++) m += h[q*13 + t];
        m *= (1.f/64.f);
        float v = 0.f;
        for (int q = 0; q < 64; q++) { float d = h[q*13+t]-m; v += d*d; }
        v *= (1.f/64.f);
        smu[tid] = m;
        srs[tid] = rsqrtf(v + 1e-5f);
    }
    __syncthreads();
    float ga = gamma[co], be = beta[co];
    float* o = out + (((size_t)(bn0+bn_l))*64 + co)*12;
    #pragma unroll
    for (int t = 0; t < 12; t++)
        o[t] = (acc[t] - smu[bn_l*12+t])*srs[bn_l*12+t]*ga + be;
}

// ---------------- launch ----------------
extern "C" void kernel_launch(void* const* d_in, const int* in_sizes, int n_in,
                              void* d_out, int out_size) {
    const float* x    = (const float*)d_in[0];
    const float* W1   = (const float*)d_in[1];
    const float* W2   = (const float*)d_in[2];
    const float* W3   = (const float*)d_in[3];
    const float* b_s  = (const float*)d_in[4];
    const float* V_s  = (const float*)d_in[5];
    const float* U1   = (const float*)d_in[6];
    const float* U2   = (const float*)d_in[7];
    const float* U3   = (const float*)d_in[8];
    const float* b_e  = (const float*)d_in[9];
    const float* V_e  = (const float*)d_in[10];
    const float* cheb = (const float*)d_in[11];
    const float* Theta= (const float*)d_in[12];
    const float* tw   = (const float*)d_in[13];
    const float* tb   = (const float*)d_in[14];
    const float* rw   = (const float*)d_in[15];
    const float* rb   = (const float*)d_in[16];
    const float* gamma= (const float*)d_in[17];
    const float* beta = (const float*)d_in[18];
    float* out = (float*)d_out;

    k_tlhs<<<BB, 768>>>(x, U1);
    k_trhs<<<(BB*NN*TT+255)/256, 256>>>(x, U3);
    k_tlhs2<<<(BB*TT*NN+255)/256, 256>>>(U2);
    k_tattn<<<BB, 160>>>(b_e, V_e);
    k_xtat_fused<<<dim3(77, BB), 256>>>(x, W1, W3);
    k_slhs2<<<(BB*NN*TT+255)/256, 256>>>(W2);
    k_sprodsig<<<(BB*NN*NN+255)/256, 256>>>(b_s);
    k_vst<<<(NNN+255)/256, 256>>>(V_s);
    k_sx<<<SPRE_BLOCKS + XT_BLOCKS, 256>>>(x, Theta);   // spre || xtheta
    k_softS<<<dim3(BB, 5), 64>>>();
    k_cheb<<<dim3(30, BB), 128>>>(cheb);   // 5 m-tiles(64) x 6 n-tiles(128)
    cudaFuncSetAttribute(k_epi, cudaFuncAttributeMaxDynamicSharedMemorySize, 112*1024);
    size_t epi_smem = (size_t)(64*193 + 64*65 + 4*768 + 4*1024 + 4*832 + 96)*sizeof(float);
    k_epi<<<MM/4, 256, epi_smem>>>(x, tw, tb, rw, rb, gamma, beta, out);
}

// round 14
// speedup vs baseline: 1.0295x; 1.0295x over previous
#include <cuda_runtime.h>
#include <math.h>
#include <stdint.h>

#define BB 64
#define NN 307
#define FF 64
#define TT 12
#define KK 3
#define CC 64
#define CT 64
#define FT (FF*TT)      // 768
#define CTT (CC*TT)     // 768
#define NNN (NN*NN)     // 94249
#define MM (BB*NN)      // 19648
#define XROW 772        // padded xs row (768 + 4) to stagger banks across ii

// ---------------- scratch (static device globals; no allocs) ----------------
__device__ __align__(16) float g_xTheta[(size_t)KK*BB*NN*CTT];   // [k,b,i,t*64+c]
__device__ __align__(16) float g_sig[BB*NNN];
__device__ __align__(16) float g_S[BB*NNN];
__device__ __align__(16) float g_sg[(size_t)BB*NN*CTT];          // [b,j,t*64+c]
__device__ __align__(16) float g_VsT[NNN];
__device__ __align__(16) float g_E[BB*TT*TT];
__device__ __align__(16) float g_tlhs[BB*TT*FF];
__device__ __align__(16) float g_tlhs2[BB*TT*NN];
__device__ __align__(16) float g_trhs[BB*NN*TT];
__device__ __align__(16) float g_slhs[BB*NN*FF];
__device__ __align__(16) float g_slhs2[BB*NN*TT];
__device__ __align__(16) float g_srhsT[BB*NN*TT];               // [b,m,t] transposed

// ---------------- temporal attention ----------------
__global__ void k_tlhs(const float* __restrict__ x, const float* __restrict__ U1) {
    int b = blockIdx.x;
    int tid = threadIdx.x;                  // tid = f*12+t
    int f = tid / TT, t = tid % TT;
    const float* xb = x + (size_t)b*NN*FT;
    float acc = 0.f;
    for (int n = 0; n < NN; n++) acc += xb[n*FT + tid] * U1[n];
    g_tlhs[(b*TT + t)*FF + f] = acc;
}

__global__ void k_trhs(const float* __restrict__ x, const float* __restrict__ U3) {
    int idx = blockIdx.x*blockDim.x + threadIdx.x;
    if (idx >= BB*NN*TT) return;
    int t = idx % TT; int bn = idx / TT;
    const float* xr = x + (size_t)bn*FT + t;
    float acc = 0.f;
    #pragma unroll
    for (int f = 0; f < FF; f++) acc += xr[f*TT] * U3[f];
    g_trhs[idx] = acc;
}

__global__ void k_tlhs2(const float* __restrict__ U2) {
    int idx = blockIdx.x*blockDim.x + threadIdx.x;
    if (idx >= BB*TT*NN) return;
    int n = idx % NN; int bt = idx / NN;
    const float* l = g_tlhs + bt*FF;
    float acc = 0.f;
    #pragma unroll
    for (int f = 0; f < FF; f++) acc += l[f]*U2[f*NN + n];
    g_tlhs2[idx] = acc;
}

__global__ void k_tattn(const float* __restrict__ b_e, const float* __restrict__ V_e) {
    int b = blockIdx.x;
    int tid = threadIdx.x;
    __shared__ float sgm[144], Es[144], cmax[TT], csum[TT];
    if (tid < 144) {
        int u = tid / TT, s = tid % TT;
        const float* l = g_tlhs2 + (b*TT + u)*NN;
        const float* r = g_trhs + (size_t)b*NN*TT + s;
        float p = 0.f;
        for (int n = 0; n < NN; n++) p += l[n]*r[n*TT];
        sgm[tid] = 1.f/(1.f + expf(-(p + b_e[tid])));
    }
    __syncthreads();
    if (tid < 144) {
        int u = tid / TT, s = tid % TT;
        float e = 0.f;
        #pragma unroll
        for (int v = 0; v < TT; v++) e += V_e[u*TT+v]*sgm[v*TT+s];
        Es[tid] = e;
    }
    __syncthreads();
    if (tid < TT) {
        float m = -1e30f;
        for (int u = 0; u < TT; u++) m = fmaxf(m, Es[u*TT+tid]);
        float s = 0.f;
        for (int u = 0; u < TT; u++) s += expf(Es[u*TT+tid]-m);
        cmax[tid] = m; csum[tid] = s;
    }
    __syncthreads();
    if (tid < 144) {
        int s = tid % TT;
        g_E[b*144 + tid] = expf(Es[tid]-cmax[s])/csum[s];
    }
}

// fused: x_TAt row -> slhs (dot with W1) and srhsT (W3-weighted reduce over f).
__global__ void __launch_bounds__(256) k_xtat_fused(const float* __restrict__ x,
                                                    const float* __restrict__ W1,
                                                    const float* __restrict__ W3) {
    int b = blockIdx.y;
    __shared__ float Es[144];
    __shared__ float part[8][TT];
    if (threadIdx.x < 144) Es[threadIdx.x] = g_E[b*144 + threadIdx.x];
    __syncthreads();
    int row = blockIdx.x*256 + threadIdx.x;     // row = n*64 + f
    bool valid = row < NN*FF;
    float xv[TT];
    if (valid) {
        const float* xr = x + ((size_t)b*NN*FF + row)*TT;
        #pragma unroll
        for (int s = 0; s < TT; s++) xv[s] = xr[s];
    } else {
        #pragma unroll
        for (int s = 0; s < TT; s++) xv[s] = 0.f;
    }
    float o[TT];
    #pragma unroll
    for (int t = 0; t < TT; t++) {
        float a = 0.f;
        #pragma unroll
        for (int s = 0; s < TT; s++) a += xv[s]*Es[s*TT+t];
        o[t] = a;
    }
    if (valid) {
        float a = 0.f;
        #pragma unroll
        for (int t = 0; t < TT; t++) a += o[t]*W1[t];
        g_slhs[(size_t)b*NN*FF + row] = a;
    }
    int f = row & 63;
    float w = valid ? W3[f] : 0.f;
    float c[TT];
    #pragma unroll
    for (int t = 0; t < TT; t++) c[t] = w*o[t];
    #pragma unroll
    for (int off = 16; off > 0; off >>= 1) {
        #pragma unroll
        for (int t = 0; t < TT; t++)
            c[t] += __shfl_down_sync(0xffffffffu, c[t], off);
    }
    int warp = threadIdx.x >> 5, lane = threadIdx.x & 31;
    if (lane == 0) {
        #pragma unroll
        for (int t = 0; t < TT; t++) part[warp][t] = c[t];
    }
    __syncthreads();
    if ((warp & 1) == 0 && lane < TT) {
        int n = (blockIdx.x*256 + 32*warp) >> 6;
        if (n < NN)
            g_srhsT[((size_t)b*NN + n)*TT + lane] = part[warp][lane] + part[warp+1][lane];
    }
}

// ---------------- spatial attention ----------------
__global__ void k_slhs2(const float* __restrict__ W2) {
    int idx = blockIdx.x*blockDim.x + threadIdx.x;
    if (idx >= BB*NN*TT) return;
    int t = idx % TT; int bn = idx / TT;
    const float* l = g_slhs + bn*FF;
    float a = 0.f;
    #pragma unroll
    for (int f = 0; f < FF; f++) a += l[f]*W2[f*TT+t];
    g_slhs2[idx] = a;
}

__global__ void k_sprodsig(const float* __restrict__ b_s) {
    int idx = blockIdx.x*blockDim.x + threadIdx.x;
    if (idx >= BB*NN*NN) return;
    int m = idx % NN; int r = idx / NN; int n = r % NN; int b = r / NN;
    const float4* l4 = (const float4*)(g_slhs2 + ((size_t)b*NN + n)*TT);
    const float4* r4 = (const float4*)(g_srhsT + ((size_t)b*NN + m)*TT);
    float4 l0 = l4[0], l1 = l4[1], l2 = l4[2];
    float4 r0 = r4[0], r1 = r4[1], r2 = r4[2];
    float p = l0.x*r0.x + l0.y*r0.y + l0.z*r0.z + l0.w*r0.w
            + l1.x*r1.x + l1.y*r1.y + l1.z*r1.z + l1.w*r1.w
            + l2.x*r2.x + l2.y*r2.y + l2.z*r2.z + l2.w*r2.w;
    g_sig[idx] = 1.f/(1.f + __expf(-(p + b_s[n*NN + m])));
}

__global__ void k_vst(const float* __restrict__ V_s) {
    int idx = blockIdx.x*blockDim.x + threadIdx.x;
    if (idx >= NNN) return;
    int i = idx % NN, v = idx / NN;
    g_VsT[v*NN + i] = V_s[i*NN + v];
}

// S_pre[m, i] = sum_v sig[m, v]*VsT[v, i]   (R6)
__global__ void __launch_bounds__(256) k_spre() {
    __shared__ __align__(16) float As[2][8][132];
    __shared__ __align__(16) float Bs[2][8][128];
    const int m0 = blockIdx.x * 128;
    const int n0 = blockIdx.y * 128;
    const int tid = threadIdx.x;
    const int tx = tid & 15, ty = tid >> 4;
    const int a_m = tid >> 1;
    const int a_v = (tid & 1) << 2;
    const int gm = m0 + a_m;
    float acc[8][8];
    #pragma unroll
    for (int r = 0; r < 8; r++)
        #pragma unroll
        for (int q = 0; q < 8; q++) acc[r][q] = 0.f;

    #pragma unroll
    for (int j = 0; j < 4; j++) {
        int v = a_v + j;
        As[0][a_v + j][a_m] = (gm < MM && v < NN) ? g_sig[(size_t)gm*NN + v] : 0.f;
    }
    #pragma unroll
    for (int p = 0; p < 4; p++) {
        int e = tid + p*256;
        int kk = e >> 7, il = e & 127;
        Bs[0][kk][il] = (kk < NN && n0+il < NN) ? g_VsT[kk*NN + n0 + il] : 0.f;
    }
    __syncthreads();
    const int NKT = 39;
    for (int kt = 0; kt < NKT; kt++) {
        int cur = kt & 1;
        float ar[4], br[4];
        if (kt + 1 < NKT) {
            int v0 = (kt+1)*8;
            #pragma unroll
            for (int j = 0; j < 4; j++) {
                int v = v0 + a_v + j;
                ar[j] = (gm < MM && v < NN) ? g_sig[(size_t)gm*NN + v] : 0.f;
            }
            #pragma unroll
            for (int p = 0; p < 4; p++) {
                int e = tid + p*256;
                int kk = e >> 7, il = e & 127;
                int v = v0 + kk, i = n0 + il;
                br[p] = (v < NN && i < NN) ? g_VsT[v*NN + i] : 0.f;
            }
        }
        #pragma unroll
        for (int kk = 0; kk < 8; kk++) {
            float4 a0 = *(const float4*)&As[cur][kk][ty*8];
            float4 a1 = *(const float4*)&As[cur][kk][ty*8+4];
            float4 b0 = *(const float4*)&Bs[cur][kk][tx*8];
            float4 b1 = *(const float4*)&Bs[cur][kk][tx*8+4];
            float av[8] = {a0.x,a0.y,a0.z,a0.w,a1.x,a1.y,a1.z,a1.w};
            float bv[8] = {b0.x,b0.y,b0.z,b0.w,b1.x,b1.y,b1.z,b1.w};
            #pragma unroll
            for (int r = 0; r < 8; r++)
                #pragma unroll
                for (int q = 0; q < 8; q++) acc[r][q] += av[r]*bv[q];
        }
        if (kt + 1 < NKT) {
            int nxt = cur ^ 1;
            #pragma unroll
            for (int j = 0; j < 4; j++) As[nxt][a_v + j][a_m] = ar[j];
            #pragma unroll
            for (int p = 0; p < 4; p++) {
                int e = tid + p*256;
                Bs[nxt][e>>7][e&127] = br[p];
            }
        }
        __syncthreads();
    }
    #pragma unroll
    for (int r = 0; r < 8; r++) {
        int m = m0 + ty*8 + r;
        if (m >= MM) continue;
        #pragma unroll
        for (int q = 0; q < 8; q++) {
            int i = n0 + tx*8 + q;
            if (i < NN) g_S[(size_t)m*NN + i] = acc[r][q];
        }
    }
}

// softmax over rows a for each (b, col i)
__global__ void __launch_bounds__(64) k_softS() {
    int b = blockIdx.x;
    int i = blockIdx.y*64 + threadIdx.x;
    if (i >= NN) return;
    float* P = g_S + (size_t)b*NNN;
    float m = -1e30f;
    for (int a = 0; a < NN; a++) m = fmaxf(m, P[a*NN+i]);
    float s = 0.f;
    for (int a = 0; a < NN; a++) {
        float e = __expf(P[a*NN+i]-m);
        s += e;
        P[a*NN+i] = e;
    }
    float inv = 1.f/s;
    for (int a = 0; a < NN; a++) P[a*NN+i] *= inv;
}

// xTheta[k,b,i,t,c] = sum_f x[b,i,f,t]*Theta[k,f,c]
// 192 threads = (ii:8, tg:3, cg:8); micro 4t x 8c -> 32 FFMA per 3 LDS.128.
__global__ void __launch_bounds__(192) k_xtheta(const float* __restrict__ x,
                                                const float* __restrict__ Theta) {
    __shared__ __align__(16) float th[64*64];       // [f][c]
    __shared__ __align__(16) float xs[8*XROW];      // [ii][f*12+t], padded rows
    const int ig = blockIdx.x;     // 0..38
    const int kb = blockIdx.y;     // 0..191
    const int b = kb & 63, k = kb >> 6;
    const int i0 = ig * 8;
    const int tid = threadIdx.x;
    for (int e = tid; e < 4096; e += 192) th[e] = Theta[k*4096 + e];
    for (int e = tid; e < 8*768; e += 192) {
        int ii = e / 768, r = e - ii*768;
        float v = 0.f;
        if (i0 + ii < NN) v = x[(size_t)(b*NN + i0 + ii)*768 + r];
        xs[ii*XROW + r] = v;
    }
    __syncthreads();
    const int cg = tid & 7;
    const int tg = (tid >> 3) % 3;
    const int ii = tid / 24;
    float acc[4][8];
    #pragma unroll
    for (int t = 0; t < 4; t++)
        #pragma unroll
        for (int q = 0; q < 8; q++) acc[t][q] = 0.f;
    const float* xrow = xs + ii*XROW + tg*4;
    const float* thc = th + cg*8;
    #pragma unroll 4
    for (int f = 0; f < 64; f++) {
        float4 xv = *(const float4*)&xrow[f*12];
        float4 w0 = *(const float4*)&thc[f*64];
        float4 w1 = *(const float4*)&thc[f*64 + 4];
        float xa[4] = {xv.x, xv.y, xv.z, xv.w};
        float wv[8] = {w0.x,w0.y,w0.z,w0.w, w1.x,w1.y,w1.z,w1.w};
        #pragma unroll
        for (int t = 0; t < 4; t++)
            #pragma unroll
            for (int q = 0; q < 8; q++) acc[t][q] += xa[t]*wv[q];
    }
    if (i0 + ii < NN) {
        float* o = &g_xTheta[(((size_t)(k*BB + b))*NN + i0 + ii)*768 + cg*8];
        #pragma unroll
        for (int t = 0; t < 4; t++) {
            float* ot = o + (tg*4 + t)*64;
            ((float4*)ot)[0] = make_float4(acc[t][0],acc[t][1],acc[t][2],acc[t][3]);
            ((float4*)ot)[1] = make_float4(acc[t][4],acc[t][5],acc[t][6],acc[t][7]);
        }
    }
}

// sg[b,j,tc] = relu( sum_k sum_i cheb[k,i,j]*S[b,i,j] * xTheta[k,b,i,tc] )
// 64x128xBK16 tiles, 8x8 micro, 128 threads, double buffered (syncs halved).
__global__ void __launch_bounds__(128) k_cheb(const float* __restrict__ cheb) {
    __shared__ __align__(16) float As[2][16][64];
    __shared__ __align__(16) float Bs[2][16][128];
    const int b = blockIdx.y;
    const int m0 = (blockIdx.x / 6) * 64;
    const int n0 = (blockIdx.x % 6) * 128;
    const int tid = threadIdx.x;
    const int tx = tid & 15, ty = tid >> 4;   // ty 0..7
    const float* Sb = g_S + (size_t)b*NNN;
    float acc[8][8];
    #pragma unroll
    for (int r = 0; r < 8; r++)
        #pragma unroll
        for (int q = 0; q < 8; q++) acc[r][q] = 0.f;

    // prologue kt=0 (k=0, i0=0)
    #pragma unroll
    for (int p = 0; p < 8; p++) {
        int e = tid + p*128;
        int kk = e >> 6, jl = e & 63;
        int i = kk, j = m0 + jl;
        float av = 0.f;
        if (i < NN && j < NN) { int id = i*NN + j; av = cheb[id]*Sb[id]; }
        As[0][kk][jl] = av;
    }
    #pragma unroll
    for (int p = 0; p < 16; p++) {
        int e = tid + p*128;
        int kk = e >> 7, cl = e & 127;
        Bs[0][kk][cl] = (kk < NN) ? g_xTheta[((size_t)b*NN + kk)*CTT + n0 + cl] : 0.f;
    }
    __syncthreads();
    const int NKT = 3*20;  // 60 tiles of 16
    for (int kt = 0; kt < NKT; kt++) {
        int cur = kt & 1;
        float ar[8], br[16];
        if (kt + 1 < NKT) {
            int kt1 = kt + 1;
            int kpoly = kt1 / 20;
            int i0 = (kt1 - kpoly*20) * 16;
            const float* Ck = cheb + (size_t)kpoly*NNN;
            const float* Xk = g_xTheta + (size_t)(kpoly*BB + b)*NN*CTT;
            #pragma unroll
            for (int p = 0; p < 8; p++) {
                int e = tid + p*128;
                int kk = e >> 6, jl = e & 63;
                int i = i0 + kk, j = m0 + jl;
                float av = 0.f;
                if (i < NN && j < NN) { int id = i*NN + j; av = Ck[id]*Sb[id]; }
                ar[p] = av;
            }
            #pragma unroll
            for (int p = 0; p < 16; p++) {
                int e = tid + p*128;
                int kk = e >> 7, cl = e & 127;
                int i = i0 + kk;
                br[p] = (i < NN) ? Xk[(size_t)i*CTT + n0 + cl] : 0.f;
            }
        }
        #pragma unroll
        for (int kk = 0; kk < 16; kk++) {
            float4 a0 = *(const float4*)&As[cur][kk][ty*8];
            float4 a1 = *(const float4*)&As[cur][kk][ty*8+4];
            float4 b0 = *(const float4*)&Bs[cur][kk][tx*8];
            float4 b1 = *(const float4*)&Bs[cur][kk][tx*8+4];
            float av[8] = {a0.x,a0.y,a0.z,a0.w,a1.x,a1.y,a1.z,a1.w};
            float bv[8] = {b0.x,b0.y,b0.z,b0.w,b1.x,b1.y,b1.z,b1.w};
            #pragma unroll
            for (int r = 0; r < 8; r++)
                #pragma unroll
                for (int q = 0; q < 8; q++) acc[r][q] += av[r]*bv[q];
        }
        if (kt + 1 < NKT) {
            int nxt = cur ^ 1;
            #pragma unroll
            for (int p = 0; p < 8; p++) {
                int e = tid + p*128;
                As[nxt][e>>6][e&63] = ar[p];
            }
            #pragma unroll
            for (int p = 0; p < 16; p++) {
                int e = tid + p*128;
                Bs[nxt][e>>7][e&127] = br[p];
            }
        }
        __syncthreads();
    }
    float* o = g_sg + (size_t)b*NN*CTT;
    #pragma unroll
    for (int r = 0; r < 8; r++) {
        int j = m0 + ty*8 + r;
        if (j >= NN) continue;
        float* orow = o + (size_t)j*CTT + n0 + tx*8;
        float4 v0 = make_float4(fmaxf(acc[r][0],0.f), fmaxf(acc[r][1],0.f),
                                fmaxf(acc[r][2],0.f), fmaxf(acc[r][3],0.f));
        float4 v1 = make_float4(fmaxf(acc[r][4],0.f), fmaxf(acc[r][5],0.f),
                                fmaxf(acc[r][6],0.f), fmaxf(acc[r][7],0.f));
        ((float4*)orow)[0] = v0;
        ((float4*)orow)[1] = v1;
    }
}

// fused: rconv + tconv + relu + LayerNorm. Block = 4 bn, 256 threads. (R6)
__global__ void __launch_bounds__(256) k_epi(
    const float* __restrict__ x, const float* __restrict__ tw, const float* __restrict__ tb,
    const float* __restrict__ rw, const float* __restrict__ rb,
    const float* __restrict__ gamma, const float* __restrict__ beta, float* __restrict__ out)
{
    extern __shared__ __align__(16) float sh[];
    float* wT  = sh;                 // 64*193
    float* wR  = wT + 64*193;        // 64*65
    float* xs  = wR + 64*65;         // 4*768
    float* sgs = xs + 4*768;         // 4*1024
    float* hs  = sgs + 4*1024;       // 4*832
    float* smu = hs + 4*832;         // 48
    float* srs = smu + 48;           // 48
    const int tid = threadIdx.x;
    const int bn_l = tid >> 6;
    const int co = tid & 63;
    const int bn0 = blockIdx.x * 4;

    for (int e = tid; e < 64*192; e += 256) wT[(e/192)*193 + (e%192)] = tw[e];
    for (int e = tid; e < 64*64;  e += 256) wR[(e>>6)*65 + (e&63)] = rw[e];
    for (int e = tid; e < 4*768;  e += 256) xs[e] = x[(size_t)bn0*768 + e];
    for (int e = tid; e < 4*1024; e += 256) sgs[e] = 0.f;
    __syncthreads();
    for (int e = tid; e < 4*768; e += 256) {
        int bl = e / 768, r = e % 768, t = r >> 6, c = r & 63;
        sgs[bl*1024 + c*16 + t + 1] = g_sg[(size_t)(bn0+bl)*768 + r];
    }
    __syncthreads();

    float acc[12];
    {
        float bias = tb[co] + rb[co];
        #pragma unroll
        for (int t = 0; t < 12; t++) acc[t] = bias;
    }
    const float* xrow = xs + bn_l*768;
    const float* wr = wR + co*65;
    #pragma unroll 4
    for (int f = 0; f < 64; f++) {
        float wf = wr[f];
        float4 x0 = *(const float4*)&xrow[f*12];
        float4 x1 = *(const float4*)&xrow[f*12+4];
        float4 x2 = *(const float4*)&xrow[f*12+8];
        acc[0] += wf*x0.x; acc[1] += wf*x0.y; acc[2]  += wf*x0.z; acc[3]  += wf*x0.w;
        acc[4] += wf*x1.x; acc[5] += wf*x1.y; acc[6]  += wf*x1.z; acc[7]  += wf*x1.w;
        acc[8] += wf*x2.x; acc[9] += wf*x2.y; acc[10] += wf*x2.z; acc[11] += wf*x2.w;
    }
    const float* sgr = sgs + bn_l*1024;
    const float* wt = wT + co*193;
    #pragma unroll 2
    for (int c = 0; c < 64; c++) {
        float w0 = wt[c*3], w1 = wt[c*3+1], w2 = wt[c*3+2];
        float4 s0 = *(const float4*)&sgr[c*16];
        float4 s1 = *(const float4*)&sgr[c*16+4];
        float4 s2 = *(const float4*)&sgr[c*16+8];
        float4 s3 = *(const float4*)&sgr[c*16+12];
        float sv[14] = {s0.x,s0.y,s0.z,s0.w, s1.x,s1.y,s1.z,s1.w,
                        s2.x,s2.y,s2.z,s2.w, s3.x,s3.y};
        #pragma unroll
        for (int t = 0; t < 12; t++)
            acc[t] += sv[t]*w0 + sv[t+1]*w1 + sv[t+2]*w2;
    }
    #pragma unroll
    for (int t = 0; t < 12; t++) {
        acc[t] = fmaxf(acc[t], 0.f);
        hs[bn_l*832 + co*13 + t] = acc[t];
    }
    __syncthreads();
    if (tid < 48) {
        int bl = tid / 12, t = tid % 12;
        const float* h = hs + bl*832;
        float m = 0.f;
        for (int q = 0; q < 64; q++) m += h[q*13 + t];
        m *= (1.f/64.f);
        float v = 0.f;
        for (int q = 0; q < 64; q++) { float d = h[q*13+t]-m; v += d*d; }
        v *= (1.f/64.f);
        smu[tid] = m;
        srs[tid] = rsqrtf(v + 1e-5f);
    }
    __syncthreads();
    float ga = gamma[co], be = beta[co];
    float* o = out + (((size_t)(bn0+bn_l))*64 + co)*12;
    #pragma unroll
    for (int t = 0; t < 12; t++)
        o[t] = (acc[t] - smu[bn_l*12+t])*srs[bn_l*12+t]*ga + be;
}

// ---------------- launch ----------------
extern "C" void kernel_launch(void* const* d_in, const int* in_sizes, int n_in,
                              void* d_out, int out_size) {
    const float* x    = (const float*)d_in[0];
    const float* W1   = (const float*)d_in[1];
    const float* W2   = (const float*)d_in[2];
    const float* W3   = (const float*)d_in[3];
    const float* b_s  = (const float*)d_in[4];
    const float* V_s  = (const float*)d_in[5];
    const float* U1   = (const float*)d_in[6];
    const float* U2   = (const float*)d_in[7];
    const float* U3   = (const float*)d_in[8];
    const float* b_e  = (const float*)d_in[9];
    const float* V_e  = (const float*)d_in[10];
    const float* cheb = (const float*)d_in[11];
    const float* Theta= (const float*)d_in[12];
    const float* tw   = (const float*)d_in[13];
    const float* tb   = (const float*)d_in[14];
    const float* rw   = (const float*)d_in[15];
    const float* rb   = (const float*)d_in[16];
    const float* gamma= (const float*)d_in[17];
    const float* beta = (const float*)d_in[18];
    float* out = (float*)d_out;

    k_tlhs<<<BB, 768>>>(x, U1);
    k_trhs<<<(BB*NN*TT+255)/256, 256>>>(x, U3);
    k_tlhs2<<<(BB*TT*NN+255)/256, 256>>>(U2);
    k_tattn<<<BB, 160>>>(b_e, V_e);
    k_xtat_fused<<<dim3(77, BB), 256>>>(x, W1, W3);
    k_slhs2<<<(BB*NN*TT+255)/256, 256>>>(W2);
    k_sprodsig<<<(BB*NN*NN+255)/256, 256>>>(b_s);
    k_vst<<<(NNN+255)/256, 256>>>(V_s);
    k_spre<<<dim3(154, 3), 256>>>();
    k_softS<<<dim3(BB, 5), 64>>>();
    k_xtheta<<<dim3(39, KK*BB), 192>>>(x, Theta);
    k_cheb<<<dim3(30, BB), 128>>>(cheb);   // 5 m-tiles(64) x 6 n-tiles(128)
    cudaFuncSetAttribute(k_epi, cudaFuncAttributeMaxDynamicSharedMemorySize, 112*1024);
    size_t epi_smem = (size_t)(64*193 + 64*65 + 4*768 + 4*1024 + 4*832 + 96)*sizeof(float);
    k_epi<<<MM/4, 256, epi_smem>>>(x, tw, tb, rw, rb, gamma, beta, out);
}

// round 16
// speedup vs baseline: 1.0321x; 1.0026x over previous
#include <cuda_runtime.h>
#include <math.h>
#include <stdint.h>

#define BB 64
#define NN 307
#define FF 64
#define TT 12
#define KK 3
#define CC 64
#define CT 64
#define FT (FF*TT)      // 768
#define CTT (CC*TT)     // 768
#define NNN (NN*NN)     // 94249
#define MM (BB*NN)      // 19648

// ---------------- scratch (static device globals; no allocs) ----------------
__device__ __align__(16) float g_xTheta[(size_t)KK*BB*NN*CTT];   // [k,b,i,t*64+c]
__device__ __align__(16) float g_sig[BB*NNN];
__device__ __align__(16) float g_S[BB*NNN];
__device__ __align__(16) float g_sg[(size_t)BB*NN*CTT];          // [b,j,t*64+c]
__device__ __align__(16) float g_VsT[NNN];
__device__ __align__(16) float g_E[BB*TT*TT];
__device__ __align__(16) float g_tlhs[BB*TT*FF];
__device__ __align__(16) float g_tlhs2[BB*TT*NN];
__device__ __align__(16) float g_trhs[BB*NN*TT];
__device__ __align__(16) float g_slhs[BB*NN*FF];
__device__ __align__(16) float g_slhs2[BB*NN*TT];
__device__ __align__(16) float g_srhsT[BB*NN*TT];               // [b,m,t] transposed

// ---------------- temporal attention ----------------
// merged: blocks [0,64) compute tlhs (per-b, 768 thr); blocks [64, 64+307)
// compute trhs elementwise.
__global__ void __launch_bounds__(768) k_tlhs_trhs(const float* __restrict__ x,
                                                   const float* __restrict__ U1,
                                                   const float* __restrict__ U3) {
    if (blockIdx.x < 64) {
        int b = blockIdx.x;
        int tid = threadIdx.x;                  // tid = f*12+t
        int f = tid / TT, t = tid % TT;
        const float* xb = x + (size_t)b*NN*FT;
        float acc = 0.f;
        for (int n = 0; n < NN; n++) acc += xb[n*FT + tid] * U1[n];
        g_tlhs[(b*TT + t)*FF + f] = acc;
    } else {
        int idx = (blockIdx.x - 64)*768 + threadIdx.x;
        if (idx >= BB*NN*TT) return;
        int t = idx % TT; int bn = idx / TT;
        const float* xr = x + (size_t)bn*FT + t;
        float acc = 0.f;
        #pragma unroll
        for (int f = 0; f < FF; f++) acc += xr[f*TT] * U3[f];
        g_trhs[idx] = acc;
    }
}

__global__ void k_tlhs2(const float* __restrict__ U2) {
    int idx = blockIdx.x*blockDim.x + threadIdx.x;
    if (idx >= BB*TT*NN) return;
    int n = idx % NN; int bt = idx / NN;
    const float* l = g_tlhs + bt*FF;
    float acc = 0.f;
    #pragma unroll
    for (int f = 0; f < FF; f++) acc += l[f]*U2[f*NN + n];
    g_tlhs2[idx] = acc;
}

__global__ void k_tattn(const float* __restrict__ b_e, const float* __restrict__ V_e) {
    int b = blockIdx.x;
    int tid = threadIdx.x;
    __shared__ float sgm[144], Es[144], cmax[TT], csum[TT];
    if (tid < 144) {
        int u = tid / TT, s = tid % TT;
        const float* l = g_tlhs2 + (b*TT + u)*NN;
        const float* r = g_trhs + (size_t)b*NN*TT + s;
        float p = 0.f;
        for (int n = 0; n < NN; n++) p += l[n]*r[n*TT];
        sgm[tid] = 1.f/(1.f + expf(-(p + b_e[tid])));
    }
    __syncthreads();
    if (tid < 144) {
        int u = tid / TT, s = tid % TT;
        float e = 0.f;
        #pragma unroll
        for (int v = 0; v < TT; v++) e += V_e[u*TT+v]*sgm[v*TT+s];
        Es[tid] = e;
    }
    __syncthreads();
    if (tid < TT) {
        float m = -1e30f;
        for (int u = 0; u < TT; u++) m = fmaxf(m, Es[u*TT+tid]);
        float s = 0.f;
        for (int u = 0; u < TT; u++) s += expf(Es[u*TT+tid]-m);
        cmax[tid] = m; csum[tid] = s;
    }
    __syncthreads();
    if (tid < 144) {
        int s = tid % TT;
        g_E[b*144 + tid] = expf(Es[tid]-cmax[s])/csum[s];
    }
}

// fused: x_TAt row -> slhs (dot with W1) and srhsT (W3-weighted reduce over f).
__global__ void __launch_bounds__(256) k_xtat_fused(const float* __restrict__ x,
                                                    const float* __restrict__ W1,
                                                    const float* __restrict__ W3) {
    int b = blockIdx.y;
    __shared__ float Es[144];
    __shared__ float part[8][TT];
    if (threadIdx.x < 144) Es[threadIdx.x] = g_E[b*144 + threadIdx.x];
    __syncthreads();
    int row = blockIdx.x*256 + threadIdx.x;     // row = n*64 + f
    bool valid = row < NN*FF;
    float xv[TT];
    if (valid) {
        const float* xr = x + ((size_t)b*NN*FF + row)*TT;
        #pragma unroll
        for (int s = 0; s < TT; s++) xv[s] = xr[s];
    } else {
        #pragma unroll
        for (int s = 0; s < TT; s++) xv[s] = 0.f;
    }
    float o[TT];
    #pragma unroll
    for (int t = 0; t < TT; t++) {
        float a = 0.f;
        #pragma unroll
        for (int s = 0; s < TT; s++) a += xv[s]*Es[s*TT+t];
        o[t] = a;
    }
    if (valid) {
        float a = 0.f;
        #pragma unroll
        for (int t = 0; t < TT; t++) a += o[t]*W1[t];
        g_slhs[(size_t)b*NN*FF + row] = a;
    }
    int f = row & 63;
    float w = valid ? W3[f] : 0.f;
    float c[TT];
    #pragma unroll
    for (int t = 0; t < TT; t++) c[t] = w*o[t];
    #pragma unroll
    for (int off = 16; off > 0; off >>= 1) {
        #pragma unroll
        for (int t = 0; t < TT; t++)
            c[t] += __shfl_down_sync(0xffffffffu, c[t], off);
    }
    int warp = threadIdx.x >> 5, lane = threadIdx.x & 31;
    if (lane == 0) {
        #pragma unroll
        for (int t = 0; t < TT; t++) part[warp][t] = c[t];
    }
    __syncthreads();
    if ((warp & 1) == 0 && lane < TT) {
        int n = (blockIdx.x*256 + 32*warp) >> 6;
        if (n < NN)
            g_srhsT[((size_t)b*NN + n)*TT + lane] = part[warp][lane] + part[warp+1][lane];
    }
}

// ---------------- spatial attention ----------------
__global__ void k_slhs2(const float* __restrict__ W2) {
    int idx = blockIdx.x*blockDim.x + threadIdx.x;
    if (idx >= BB*NN*TT) return;
    int t = idx % TT; int bn = idx / TT;
    const float* l = g_slhs + bn*FF;
    float a = 0.f;
    #pragma unroll
    for (int f = 0; f < FF; f++) a += l[f]*W2[f*TT+t];
    g_slhs2[idx] = a;
}

// merged: main range computes sig; tail range transposes V_s into g_VsT.
__global__ void k_sprodsig(const float* __restrict__ b_s, const float* __restrict__ V_s) {
    int idx = blockIdx.x*blockDim.x + threadIdx.x;
    if (idx < BB*NN*NN) {
        int m = idx % NN; int r = idx / NN; int n = r % NN; int b = r / NN;
        const float4* l4 = (const float4*)(g_slhs2 + ((size_t)b*NN + n)*TT);
        const float4* r4 = (const float4*)(g_srhsT + ((size_t)b*NN + m)*TT);
        float4 l0 = l4[0], l1 = l4[1], l2 = l4[2];
        float4 r0 = r4[0], r1 = r4[1], r2 = r4[2];
        float p = l0.x*r0.x + l0.y*r0.y + l0.z*r0.z + l0.w*r0.w
                + l1.x*r1.x + l1.y*r1.y + l1.z*r1.z + l1.w*r1.w
                + l2.x*r2.x + l2.y*r2.y + l2.z*r2.z + l2.w*r2.w;
        g_sig[idx] = 1.f/(1.f + __expf(-(p + b_s[n*NN + m])));
    } else {
        int e = idx - BB*NN*NN;
        if (e < NNN) {
            int i = e % NN, v = e / NN;
            g_VsT[v*NN + i] = V_s[i*NN + v];
        }
    }
}

// S_pre[m, i] = sum_v sig[m, v]*VsT[v, i]   (R6)
__global__ void __launch_bounds__(256) k_spre() {
    __shared__ __align__(16) float As[2][8][132];
    __shared__ __align__(16) float Bs[2][8][128];
    const int m0 = blockIdx.x * 128;
    const int n0 = blockIdx.y * 128;
    const int tid = threadIdx.x;
    const int tx = tid & 15, ty = tid >> 4;
    const int a_m = tid >> 1;
    const int a_v = (tid & 1) << 2;
    const int gm = m0 + a_m;
    float acc[8][8];
    #pragma unroll
    for (int r = 0; r < 8; r++)
        #pragma unroll
        for (int q = 0; q < 8; q++) acc[r][q] = 0.f;

    #pragma unroll
    for (int j = 0; j < 4; j++) {
        int v = a_v + j;
        As[0][a_v + j][a_m] = (gm < MM && v < NN) ? g_sig[(size_t)gm*NN + v] : 0.f;
    }
    #pragma unroll
    for (int p = 0; p < 4; p++) {
        int e = tid + p*256;
        int kk = e >> 7, il = e & 127;
        Bs[0][kk][il] = (kk < NN && n0+il < NN) ? g_VsT[kk*NN + n0 + il] : 0.f;
    }
    __syncthreads();
    const int NKT = 39;
    for (int kt = 0; kt < NKT; kt++) {
        int cur = kt & 1;
        float ar[4], br[4];
        if (kt + 1 < NKT) {
            int v0 = (kt+1)*8;
            #pragma unroll
            for (int j = 0; j < 4; j++) {
                int v = v0 + a_v + j;
                ar[j] = (gm < MM && v < NN) ? g_sig[(size_t)gm*NN + v] : 0.f;
            }
            #pragma unroll
            for (int p = 0; p < 4; p++) {
                int e = tid + p*256;
                int kk = e >> 7, il = e & 127;
                int v = v0 + kk, i = n0 + il;
                br[p] = (v < NN && i < NN) ? g_VsT[v*NN + i] : 0.f;
            }
        }
        #pragma unroll
        for (int kk = 0; kk < 8; kk++) {
            float4 a0 = *(const float4*)&As[cur][kk][ty*8];
            float4 a1 = *(const float4*)&As[cur][kk][ty*8+4];
            float4 b0 = *(const float4*)&Bs[cur][kk][tx*8];
            float4 b1 = *(const float4*)&Bs[cur][kk][tx*8+4];
            float av[8] = {a0.x,a0.y,a0.z,a0.w,a1.x,a1.y,a1.z,a1.w};
            float bv[8] = {b0.x,b0.y,b0.z,b0.w,b1.x,b1.y,b1.z,b1.w};
            #pragma unroll
            for (int r = 0; r < 8; r++)
                #pragma unroll
                for (int q = 0; q < 8; q++) acc[r][q] += av[r]*bv[q];
        }
        if (kt + 1 < NKT) {
            int nxt = cur ^ 1;
            #pragma unroll
            for (int j = 0; j < 4; j++) As[nxt][a_v + j][a_m] = ar[j];
            #pragma unroll
            for (int p = 0; p < 4; p++) {
                int e = tid + p*256;
                Bs[nxt][e>>7][e&127] = br[p];
            }
        }
        __syncthreads();
    }
    #pragma unroll
    for (int r = 0; r < 8; r++) {
        int m = m0 + ty*8 + r;
        if (m >= MM) continue;
        #pragma unroll
        for (int q = 0; q < 8; q++) {
            int i = n0 + tx*8 + q;
            if (i < NN) g_S[(size_t)m*NN + i] = acc[r][q];
        }
    }
}

// softmax over rows a for each (b, col i)
__global__ void __launch_bounds__(64) k_softS() {
    int b = blockIdx.x;
    int i = blockIdx.y*64 + threadIdx.x;
    if (i >= NN) return;
    float* P = g_S + (size_t)b*NNN;
    float m = -1e30f;
    for (int a = 0; a < NN; a++) m = fmaxf(m, P[a*NN+i]);
    float s = 0.f;
    for (int a = 0; a < NN; a++) {
        float e = __expf(P[a*NN+i]-m);
        s += e;
        P[a*NN+i] = e;
    }
    float inv = 1.f/s;
    for (int a = 0; a < NN; a++) P[a*NN+i] *= inv;
}

// xTheta[k,b,i,t,c] = sum_f x[b,i,f,t]*Theta[k,f,c]   (R6)
__global__ void __launch_bounds__(192) k_xtheta(const float* __restrict__ x,
                                                const float* __restrict__ Theta) {
    __shared__ __align__(16) float th[64*64];
    __shared__ __align__(16) float xs2[64*96];
    const int ig = blockIdx.x;     // 0..38
    const int kb = blockIdx.y;     // 0..191
    const int b = kb & 63, k = kb >> 6;
    const int i0 = ig * 8;
    const int tid = threadIdx.x;
    for (int e = tid; e < 4096; e += 192) th[e] = Theta[k*4096 + e];
    for (int e = tid; e < 8*768; e += 192) {
        int ii = e / 768, r = e % 768;
        int f = r / 12, t = r % 12;
        float v = 0.f;
        if (i0 + ii < NN) v = x[(((size_t)(b*NN + i0 + ii))*64 + f)*12 + t];
        xs2[f*96 + t*8 + ii] = v;
    }
    __syncthreads();
    const int cg = tid / 96;
    const int r2 = tid % 96;
    const int t = r2 >> 3, ii = r2 & 7;
    float acc[32];
    #pragma unroll
    for (int j = 0; j < 32; j++) acc[j] = 0.f;
    const float* xv = xs2 + t*8 + ii;
    const float* thc = th + cg*32;
    #pragma unroll 4
    for (int f = 0; f < 64; f++) {
        float xvf = xv[f*96];
        const float4* tp = (const float4*)(thc + f*64);
        #pragma unroll
        for (int j4 = 0; j4 < 8; j4++) {
            float4 w = tp[j4];
            acc[j4*4+0] += xvf*w.x; acc[j4*4+1] += xvf*w.y;
            acc[j4*4+2] += xvf*w.z; acc[j4*4+3] += xvf*w.w;
        }
    }
    if (i0 + ii < NN) {
        float* o = &g_xTheta[(((size_t)(k*BB + b))*NN + i0 + ii)*768 + t*64 + cg*32];
        #pragma unroll
        for (int j4 = 0; j4 < 8; j4++)
            ((float4*)o)[j4] = make_float4(acc[j4*4],acc[j4*4+1],acc[j4*4+2],acc[j4*4+3]);
    }
}

// sg[b,j,tc] = relu( sum_k sum_i cheb[k,i,j]*S[b,i,j] * xTheta[k,b,i,tc] )
// 64x128x8 tiles, 8x8 micro, 128 threads, double buffered, k-loop fused. (R6)
__global__ void __launch_bounds__(128) k_cheb(const float* __restrict__ cheb) {
    __shared__ __align__(16) float As[2][8][64];
    __shared__ __align__(16) float Bs[2][8][128];
    const int b = blockIdx.y;
    const int m0 = (blockIdx.x / 6) * 64;
    const int n0 = (blockIdx.x % 6) * 128;
    const int tid = threadIdx.x;
    const int tx = tid & 15, ty = tid >> 4;   // ty 0..7
    const float* Sb = g_S + (size_t)b*NNN;
    float acc[8][8];
    #pragma unroll
    for (int r = 0; r < 8; r++)
        #pragma unroll
        for (int q = 0; q < 8; q++) acc[r][q] = 0.f;

    // prologue kt=0 (k=0, i0=0)
    #pragma unroll
    for (int p = 0; p < 4; p++) {
        int e = tid + p*128;
        int kk = e >> 6, jl = e & 63;
        int i = kk, j = m0 + jl;
        float av = 0.f;
        if (i < NN && j < NN) { int id = i*NN + j; av = cheb[id]*Sb[id]; }
        As[0][kk][jl] = av;
    }
    #pragma unroll
    for (int p = 0; p < 8; p++) {
        int e = tid + p*128;
        int kk = e >> 7, cl = e & 127;
        Bs[0][kk][cl] = (kk < NN) ? g_xTheta[((size_t)b*NN + kk)*CTT + n0 + cl] : 0.f;
    }
    __syncthreads();
    const int NKT = 3*39;  // 117
    for (int kt = 0; kt < NKT; kt++) {
        int cur = kt & 1;
        float ar[4], br[8];
        if (kt + 1 < NKT) {
            int kt1 = kt + 1;
            int kpoly = kt1 / 39;
            int i0 = (kt1 - kpoly*39) * 8;
            const float* Ck = cheb + kpoly*NNN;
            const float* Xk = g_xTheta + (size_t)(kpoly*BB + b)*NN*CTT;
            #pragma unroll
            for (int p = 0; p < 4; p++) {
                int e = tid + p*128;
                int kk = e >> 6, jl = e & 63;
                int i = i0 + kk, j = m0 + jl;
                float av = 0.f;
                if (i < NN && j < NN) { int id = i*NN + j; av = Ck[id]*Sb[id]; }
                ar[p] = av;
            }
            #pragma unroll
            for (int p = 0; p < 8; p++) {
                int e = tid + p*128;
                int kk = e >> 7, cl = e & 127;
                int i = i0 + kk;
                br[p] = (i < NN) ? Xk[(size_t)i*CTT + n0 + cl] : 0.f;
            }
        }
        #pragma unroll
        for (int kk = 0; kk < 8; kk++) {
            float4 a0 = *(const float4*)&As[cur][kk][ty*8];
            float4 a1 = *(const float4*)&As[cur][kk][ty*8+4];
            float4 b0 = *(const float4*)&Bs[cur][kk][tx*8];
            float4 b1 = *(const float4*)&Bs[cur][kk][tx*8+4];
            float av[8] = {a0.x,a0.y,a0.z,a0.w,a1.x,a1.y,a1.z,a1.w};
            float bv[8] = {b0.x,b0.y,b0.z,b0.w,b1.x,b1.y,b1.z,b1.w};
            #pragma unroll
            for (int r = 0; r < 8; r++)
                #pragma unroll
                for (int q = 0; q < 8; q++) acc[r][q] += av[r]*bv[q];
        }
        if (kt + 1 < NKT) {
            int nxt = cur ^ 1;
            #pragma unroll
            for (int p = 0; p < 4; p++) {
                int e = tid + p*128;
                As[nxt][e>>6][e&63] = ar[p];
            }
            #pragma unroll
            for (int p = 0; p < 8; p++) {
                int e = tid + p*128;
                Bs[nxt][e>>7][e&127] = br[p];
            }
        }
        __syncthreads();
    }
    float* o = g_sg + (size_t)b*NN*CTT;
    #pragma unroll
    for (int r = 0; r < 8; r++) {
        int j = m0 + ty*8 + r;
        if (j >= NN) continue;
        float* orow = o + (size_t)j*CTT + n0 + tx*8;
        float4 v0 = make_float4(fmaxf(acc[r][0],0.f), fmaxf(acc[r][1],0.f),
                                fmaxf(acc[r][2],0.f), fmaxf(acc[r][3],0.f));
        float4 v1 = make_float4(fmaxf(acc[r][4],0.f), fmaxf(acc[r][5],0.f),
                                fmaxf(acc[r][6],0.f), fmaxf(acc[r][7],0.f));
        ((float4*)orow)[0] = v0;
        ((float4*)orow)[1] = v1;
    }
}

// fused: rconv + tconv + relu + LayerNorm. Block = 4 bn, 256 threads. (R6)
__global__ void __launch_bounds__(256) k_epi(
    const float* __restrict__ x, const float* __restrict__ tw, const float* __restrict__ tb,
    const float* __restrict__ rw, const float* __restrict__ rb,
    const float* __restrict__ gamma, const float* __restrict__ beta, float* __restrict__ out)
{
    extern __shared__ __align__(16) float sh[];
    float* wT  = sh;                 // 64*193
    float* wR  = wT + 64*193;        // 64*65
    float* xs  = wR + 64*65;         // 4*768
    float* sgs = xs + 4*768;         // 4*1024
    float* hs  = sgs + 4*1024;       // 4*832
    float* smu = hs + 4*832;         // 48
    float* srs = smu + 48;           // 48
    const int tid = threadIdx.x;
    const int bn_l = tid >> 6;
    const int co = tid & 63;
    const int bn0 = blockIdx.x * 4;

    for (int e = tid; e < 64*192; e += 256) wT[(e/192)*193 + (e%192)] = tw[e];
    for (int e = tid; e < 64*64;  e += 256) wR[(e>>6)*65 + (e&63)] = rw[e];
    for (int e = tid; e < 4*768;  e += 256) xs[e] = x[(size_t)bn0*768 + e];
    for (int e = tid; e < 4*1024; e += 256) sgs[e] = 0.f;
    __syncthreads();
    for (int e = tid; e < 4*768; e += 256) {
        int bl = e / 768, r = e % 768, t = r >> 6, c = r & 63;
        sgs[bl*1024 + c*16 + t + 1] = g_sg[(size_t)(bn0+bl)*768 + r];
    }
    __syncthreads();

    float acc[12];
    {
        float bias = tb[co] + rb[co];
        #pragma unroll
        for (int t = 0; t < 12; t++) acc[t] = bias;
    }
    const float* xrow = xs + bn_l*768;
    const float* wr = wR + co*65;
    #pragma unroll 4
    for (int f = 0; f < 64; f++) {
        float wf = wr[f];
        float4 x0 = *(const float4*)&xrow[f*12];
        float4 x1 = *(const float4*)&xrow[f*12+4];
        float4 x2 = *(const float4*)&xrow[f*12+8];
        acc[0] += wf*x0.x; acc[1] += wf*x0.y; acc[2]  += wf*x0.z; acc[3]  += wf*x0.w;
        acc[4] += wf*x1.x; acc[5] += wf*x1.y; acc[6]  += wf*x1.z; acc[7]  += wf*x1.w;
        acc[8] += wf*x2.x; acc[9] += wf*x2.y; acc[10] += wf*x2.z; acc[11] += wf*x2.w;
    }
    const float* sgr = sgs + bn_l*1024;
    const float* wt = wT + co*193;
    #pragma unroll 2
    for (int c = 0; c < 64; c++) {
        float w0 = wt[c*3], w1 = wt[c*3+1], w2 = wt[c*3+2];
        float4 s0 = *(const float4*)&sgr[c*16];
        float4 s1 = *(const float4*)&sgr[c*16+4];
        float4 s2 = *(const float4*)&sgr[c*16+8];
        float4 s3 = *(const float4*)&sgr[c*16+12];
        float sv[14] = {s0.x,s0.y,s0.z,s0.w, s1.x,s1.y,s1.z,s1.w,
                        s2.x,s2.y,s2.z,s2.w, s3.x,s3.y};
        #pragma unroll
        for (int t = 0; t < 12; t++)
            acc[t] += sv[t]*w0 + sv[t+1]*w1 + sv[t+2]*w2;
    }
    #pragma unroll
    for (int t = 0; t < 12; t++) {
        acc[t] = fmaxf(acc[t], 0.f);
        hs[bn_l*832 + co*13 + t] = acc[t];
    }
    __syncthreads();
    if (tid < 48) {
        int bl = tid / 12, t = tid % 12;
        const float* h = hs + bl*832;
        float m = 0.f;
        for (int q = 0; q < 64; q++) m += h[q*13 + t];
        m *= (1.f/64.f);
        float v = 0.f;
        for (int q = 0; q < 64; q++) { float d = h[q*13+t]-m; v += d*d; }
        v *= (1.f/64.f);
        smu[tid] = m;
        srs[tid] = rsqrtf(v + 1e-5f);
    }
    __syncthreads();
    float ga = gamma[co], be = beta[co];
    float* o = out + (((size_t)(bn0+bn_l))*64 + co)*12;
    #pragma unroll
    for (int t = 0; t < 12; t++)
        o[t] = (acc[t] - smu[bn_l*12+t])*srs[bn_l*12+t]*ga + be;
}

// ---------------- launch ----------------
extern "C" void kernel_launch(void* const* d_in, const int* in_sizes, int n_in,
                              void* d_out, int out_size) {
    const float* x    = (const float*)d_in[0];
    const float* W1   = (const float*)d_in[1];
    const float* W2   = (const float*)d_in[2];
    const float* W3   = (const float*)d_in[3];
    const float* b_s  = (const float*)d_in[4];
    const float* V_s  = (const float*)d_in[5];
    const float* U1   = (const float*)d_in[6];
    const float* U2   = (const float*)d_in[7];
    const float* U3   = (const float*)d_in[8];
    const float* b_e  = (const float*)d_in[9];
    const float* V_e  = (const float*)d_in[10];
    const float* cheb = (const float*)d_in[11];
    const float* Theta= (const float*)d_in[12];
    const float* tw   = (const float*)d_in[13];
    const float* tb   = (const float*)d_in[14];
    const float* rw   = (const float*)d_in[15];
    const float* rb   = (const float*)d_in[16];
    const float* gamma= (const float*)d_in[17];
    const float* beta = (const float*)d_in[18];
    float* out = (float*)d_out;

    k_tlhs_trhs<<<64 + 307, 768>>>(x, U1, U3);
    k_tlhs2<<<(BB*TT*NN+255)/256, 256>>>(U2);
    k_tattn<<<BB, 160>>>(b_e, V_e);
    k_xtat_fused<<<dim3(77, BB), 256>>>(x, W1, W3);
    k_slhs2<<<(BB*NN*TT+255)/256, 256>>>(W2);
    k_sprodsig<<<(BB*NN*NN + NNN + 255)/256, 256>>>(b_s, V_s);
    k_spre<<<dim3(154, 3), 256>>>();
    k_softS<<<dim3(BB, 5), 64>>>();
    k_xtheta<<<dim3(39, KK*BB), 192>>>(x, Theta);
    k_cheb<<<dim3(30, BB), 128>>>(cheb);   // 5 m-tiles(64) x 6 n-tiles(128)
    cudaFuncSetAttribute(k_epi, cudaFuncAttributeMaxDynamicSharedMemorySize, 112*1024);
    size_t epi_smem = (size_t)(64*193 + 64*65 + 4*768 + 4*1024 + 4*832 + 96)*sizeof(float);
    k_epi<<<MM/4, 256, epi_smem>>>(x, tw, tb, rw, rb, gamma, beta, out);
}

// round 17
// speedup vs baseline: 1.0485x; 1.0158x over previous
#include <cuda_runtime.h>
#include <math.h>
#include <stdint.h>

#define BB 64
#define NN 307
#define FF 64
#define TT 12
#define KK 3
#define CC 64
#define CT 64
#define FT (FF*TT)      // 768
#define CTT (CC*TT)     // 768
#define NNN (NN*NN)     // 94249
#define MM (BB*NN)      // 19648

// ---------------- scratch (static device globals; no allocs) ----------------
__device__ __align__(16) float g_xTheta[(size_t)KK*BB*NN*CTT];   // [k,b,i,t*64+c]
__device__ __align__(16) float g_sig[BB*NNN];
__device__ __align__(16) float g_S[BB*NNN];
__device__ __align__(16) float g_sg[(size_t)BB*NN*CTT];          // [b,j,t*64+c]
__device__ __align__(16) float g_VsT[NNN];
__device__ __align__(16) float g_E[BB*TT*TT];
__device__ __align__(16) float g_tlhs[BB*TT*FF];
__device__ __align__(16) float g_tlhs2[BB*TT*NN];
__device__ __align__(16) float g_trhs[BB*NN*TT];
__device__ __align__(16) float g_slhs[BB*NN*FF];
__device__ __align__(16) float g_slhs2[BB*NN*TT];
__device__ __align__(16) float g_srhsT[BB*NN*TT];               // [b,m,t] transposed

// ---------------- temporal attention ----------------
// merged: blocks [0,64) compute tlhs (per-b, 768 thr); blocks [64, 64+307)
// compute trhs elementwise.
__global__ void __launch_bounds__(768) k_tlhs_trhs(const float* __restrict__ x,
                                                   const float* __restrict__ U1,
                                                   const float* __restrict__ U3) {
    if (blockIdx.x < 64) {
        int b = blockIdx.x;
        int tid = threadIdx.x;                  // tid = f*12+t
        int f = tid / TT, t = tid % TT;
        const float* xb = x + (size_t)b*NN*FT;
        float acc = 0.f;
        for (int n = 0; n < NN; n++) acc += xb[n*FT + tid] * U1[n];
        g_tlhs[(b*TT + t)*FF + f] = acc;
    } else {
        int idx = (blockIdx.x - 64)*768 + threadIdx.x;
        if (idx >= BB*NN*TT) return;
        int t = idx % TT; int bn = idx / TT;
        const float* xr = x + (size_t)bn*FT + t;
        float acc = 0.f;
        #pragma unroll
        for (int f = 0; f < FF; f++) acc += xr[f*TT] * U3[f];
        g_trhs[idx] = acc;
    }
}

__global__ void k_tlhs2(const float* __restrict__ U2) {
    int idx = blockIdx.x*blockDim.x + threadIdx.x;
    if (idx >= BB*TT*NN) return;
    int n = idx % NN; int bt = idx / NN;
    const float* l = g_tlhs + bt*FF;
    float acc = 0.f;
    #pragma unroll
    for (int f = 0; f < FF; f++) acc += l[f]*U2[f*NN + n];
    g_tlhs2[idx] = acc;
}

__global__ void k_tattn(const float* __restrict__ b_e, const float* __restrict__ V_e) {
    int b = blockIdx.x;
    int tid = threadIdx.x;
    __shared__ float sgm[144], Es[144], cmax[TT], csum[TT];
    if (tid < 144) {
        int u = tid / TT, s = tid % TT;
        const float* l = g_tlhs2 + (b*TT + u)*NN;
        const float* r = g_trhs + (size_t)b*NN*TT + s;
        float p = 0.f;
        for (int n = 0; n < NN; n++) p += l[n]*r[n*TT];
        sgm[tid] = 1.f/(1.f + expf(-(p + b_e[tid])));
    }
    __syncthreads();
    if (tid < 144) {
        int u = tid / TT, s = tid % TT;
        float e = 0.f;
        #pragma unroll
        for (int v = 0; v < TT; v++) e += V_e[u*TT+v]*sgm[v*TT+s];
        Es[tid] = e;
    }
    __syncthreads();
    if (tid < TT) {
        float m = -1e30f;
        for (int u = 0; u < TT; u++) m = fmaxf(m, Es[u*TT+tid]);
        float s = 0.f;
        for (int u = 0; u < TT; u++) s += expf(Es[u*TT+tid]-m);
        cmax[tid] = m; csum[tid] = s;
    }
    __syncthreads();
    if (tid < 144) {
        int s = tid % TT;
        g_E[b*144 + tid] = expf(Es[tid]-cmax[s])/csum[s];
    }
}

// fused: x_TAt row -> slhs (dot with W1) and srhsT (W3-weighted reduce over f).
__global__ void __launch_bounds__(256) k_xtat_fused(const float* __restrict__ x,
                                                    const float* __restrict__ W1,
                                                    const float* __restrict__ W3) {
    int b = blockIdx.y;
    __shared__ float Es[144];
    __shared__ float part[8][TT];
    if (threadIdx.x < 144) Es[threadIdx.x] = g_E[b*144 + threadIdx.x];
    __syncthreads();
    int row = blockIdx.x*256 + threadIdx.x;     // row = n*64 + f
    bool valid = row < NN*FF;
    float xv[TT];
    if (valid) {
        const float* xr = x + ((size_t)b*NN*FF + row)*TT;
        #pragma unroll
        for (int s = 0; s < TT; s++) xv[s] = xr[s];
    } else {
        #pragma unroll
        for (int s = 0; s < TT; s++) xv[s] = 0.f;
    }
    float o[TT];
    #pragma unroll
    for (int t = 0; t < TT; t++) {
        float a = 0.f;
        #pragma unroll
        for (int s = 0; s < TT; s++) a += xv[s]*Es[s*TT+t];
        o[t] = a;
    }
    if (valid) {
        float a = 0.f;
        #pragma unroll
        for (int t = 0; t < TT; t++) a += o[t]*W1[t];
        g_slhs[(size_t)b*NN*FF + row] = a;
    }
    int f = row & 63;
    float w = valid ? W3[f] : 0.f;
    float c[TT];
    #pragma unroll
    for (int t = 0; t < TT; t++) c[t] = w*o[t];
    #pragma unroll
    for (int off = 16; off > 0; off >>= 1) {
        #pragma unroll
        for (int t = 0; t < TT; t++)
            c[t] += __shfl_down_sync(0xffffffffu, c[t], off);
    }
    int warp = threadIdx.x >> 5, lane = threadIdx.x & 31;
    if (lane == 0) {
        #pragma unroll
        for (int t = 0; t < TT; t++) part[warp][t] = c[t];
    }
    __syncthreads();
    if ((warp & 1) == 0 && lane < TT) {
        int n = (blockIdx.x*256 + 32*warp) >> 6;
        if (n < NN)
            g_srhsT[((size_t)b*NN + n)*TT + lane] = part[warp][lane] + part[warp+1][lane];
    }
}

// ---------------- spatial attention ----------------
__global__ void k_slhs2(const float* __restrict__ W2) {
    int idx = blockIdx.x*blockDim.x + threadIdx.x;
    if (idx >= BB*NN*TT) return;
    int t = idx % TT; int bn = idx / TT;
    const float* l = g_slhs + bn*FF;
    float a = 0.f;
    #pragma unroll
    for (int f = 0; f < FF; f++) a += l[f]*W2[f*TT+t];
    g_slhs2[idx] = a;
}

// merged: main range computes sig; tail range transposes V_s into g_VsT.
__global__ void k_sprodsig(const float* __restrict__ b_s, const float* __restrict__ V_s) {
    int idx = blockIdx.x*blockDim.x + threadIdx.x;
    if (idx < BB*NN*NN) {
        int m = idx % NN; int r = idx / NN; int n = r % NN; int b = r / NN;
        const float4* l4 = (const float4*)(g_slhs2 + ((size_t)b*NN + n)*TT);
        const float4* r4 = (const float4*)(g_srhsT + ((size_t)b*NN + m)*TT);
        float4 l0 = l4[0], l1 = l4[1], l2 = l4[2];
        float4 r0 = r4[0], r1 = r4[1], r2 = r4[2];
        float p = l0.x*r0.x + l0.y*r0.y + l0.z*r0.z + l0.w*r0.w
                + l1.x*r1.x + l1.y*r1.y + l1.z*r1.z + l1.w*r1.w
                + l2.x*r2.x + l2.y*r2.y + l2.z*r2.z + l2.w*r2.w;
        g_sig[idx] = 1.f/(1.f + __expf(-(p + b_s[n*NN + m])));
    } else {
        int e = idx - BB*NN*NN;
        if (e < NNN) {
            int i = e % NN, v = e / NN;
            g_VsT[v*NN + i] = V_s[i*NN + v];
        }
    }
}

// S_pre[m, i] = sum_v sig[m, v]*VsT[v, i]   (R6)
__global__ void __launch_bounds__(256) k_spre() {
    __shared__ __align__(16) float As[2][8][132];
    __shared__ __align__(16) float Bs[2][8][128];
    const int m0 = blockIdx.x * 128;
    const int n0 = blockIdx.y * 128;
    const int tid = threadIdx.x;
    const int tx = tid & 15, ty = tid >> 4;
    const int a_m = tid >> 1;
    const int a_v = (tid & 1) << 2;
    const int gm = m0 + a_m;
    float acc[8][8];
    #pragma unroll
    for (int r = 0; r < 8; r++)
        #pragma unroll
        for (int q = 0; q < 8; q++) acc[r][q] = 0.f;

    #pragma unroll
    for (int j = 0; j < 4; j++) {
        int v = a_v + j;
        As[0][a_v + j][a_m] = (gm < MM && v < NN) ? g_sig[(size_t)gm*NN + v] : 0.f;
    }
    #pragma unroll
    for (int p = 0; p < 4; p++) {
        int e = tid + p*256;
        int kk = e >> 7, il = e & 127;
        Bs[0][kk][il] = (kk < NN && n0+il < NN) ? g_VsT[kk*NN + n0 + il] : 0.f;
    }
    __syncthreads();
    const int NKT = 39;
    for (int kt = 0; kt < NKT; kt++) {
        int cur = kt & 1;
        float ar[4], br[4];
        if (kt + 1 < NKT) {
            int v0 = (kt+1)*8;
            #pragma unroll
            for (int j = 0; j < 4; j++) {
                int v = v0 + a_v + j;
                ar[j] = (gm < MM && v < NN) ? g_sig[(size_t)gm*NN + v] : 0.f;
            }
            #pragma unroll
            for (int p = 0; p < 4; p++) {
                int e = tid + p*256;
                int kk = e >> 7, il = e & 127;
                int v = v0 + kk, i = n0 + il;
                br[p] = (v < NN && i < NN) ? g_VsT[v*NN + i] : 0.f;
            }
        }
        #pragma unroll
        for (int kk = 0; kk < 8; kk++) {
            float4 a0 = *(const float4*)&As[cur][kk][ty*8];
            float4 a1 = *(const float4*)&As[cur][kk][ty*8+4];
            float4 b0 = *(const float4*)&Bs[cur][kk][tx*8];
            float4 b1 = *(const float4*)&Bs[cur][kk][tx*8+4];
            float av[8] = {a0.x,a0.y,a0.z,a0.w,a1.x,a1.y,a1.z,a1.w};
            float bv[8] = {b0.x,b0.y,b0.z,b0.w,b1.x,b1.y,b1.z,b1.w};
            #pragma unroll
            for (int r = 0; r < 8; r++)
                #pragma unroll
                for (int q = 0; q < 8; q++) acc[r][q] += av[r]*bv[q];
        }
        if (kt + 1 < NKT) {
            int nxt = cur ^ 1;
            #pragma unroll
            for (int j = 0; j < 4; j++) As[nxt][a_v + j][a_m] = ar[j];
            #pragma unroll
            for (int p = 0; p < 4; p++) {
                int e = tid + p*256;
                Bs[nxt][e>>7][e&127] = br[p];
            }
        }
        __syncthreads();
    }
    #pragma unroll
    for (int r = 0; r < 8; r++) {
        int m = m0 + ty*8 + r;
        if (m >= MM) continue;
        #pragma unroll
        for (int q = 0; q < 8; q++) {
            int i = n0 + tx*8 + q;
            if (i < NN) g_S[(size_t)m*NN + i] = acc[r][q];
        }
    }
}

// softmax over rows a for each (b, col i)
__global__ void __launch_bounds__(64) k_softS() {
    int b = blockIdx.x;
    int i = blockIdx.y*64 + threadIdx.x;
    if (i >= NN) return;
    float* P = g_S + (size_t)b*NNN;
    float m = -1e30f;
    for (int a = 0; a < NN; a++) m = fmaxf(m, P[a*NN+i]);
    float s = 0.f;
    for (int a = 0; a < NN; a++) {
        float e = __expf(P[a*NN+i]-m);
        s += e;
        P[a*NN+i] = e;
    }
    float inv = 1.f/s;
    for (int a = 0; a < NN; a++) P[a*NN+i] *= inv;
}

// xTheta[k,b,i,t,c] = sum_f x[b,i,f,t]*Theta[k,f,c]   (R6)
__global__ void __launch_bounds__(192) k_xtheta(const float* __restrict__ x,
                                                const float* __restrict__ Theta) {
    __shared__ __align__(16) float th[64*64];
    __shared__ __align__(16) float xs2[64*96];
    const int ig = blockIdx.x;     // 0..38
    const int kb = blockIdx.y;     // 0..191
    const int b = kb & 63, k = kb >> 6;
    const int i0 = ig * 8;
    const int tid = threadIdx.x;
    for (int e = tid; e < 4096; e += 192) th[e] = Theta[k*4096 + e];
    for (int e = tid; e < 8*768; e += 192) {
        int ii = e / 768, r = e % 768;
        int f = r / 12, t = r % 12;
        float v = 0.f;
        if (i0 + ii < NN) v = x[(((size_t)(b*NN + i0 + ii))*64 + f)*12 + t];
        xs2[f*96 + t*8 + ii] = v;
    }
    __syncthreads();
    const int cg = tid / 96;
    const int r2 = tid % 96;
    const int t = r2 >> 3, ii = r2 & 7;
    float acc[32];
    #pragma unroll
    for (int j = 0; j < 32; j++) acc[j] = 0.f;
    const float* xv = xs2 + t*8 + ii;
    const float* thc = th + cg*32;
    #pragma unroll 4
    for (int f = 0; f < 64; f++) {
        float xvf = xv[f*96];
        const float4* tp = (const float4*)(thc + f*64);
        #pragma unroll
        for (int j4 = 0; j4 < 8; j4++) {
            float4 w = tp[j4];
            acc[j4*4+0] += xvf*w.x; acc[j4*4+1] += xvf*w.y;
            acc[j4*4+2] += xvf*w.z; acc[j4*4+3] += xvf*w.w;
        }
    }
    if (i0 + ii < NN) {
        float* o = &g_xTheta[(((size_t)(k*BB + b))*NN + i0 + ii)*768 + t*64 + cg*32];
        #pragma unroll
        for (int j4 = 0; j4 < 8; j4++)
            ((float4*)o)[j4] = make_float4(acc[j4*4],acc[j4*4+1],acc[j4*4+2],acc[j4*4+3]);
    }
}

// sg[b,j,tc] = relu( sum_k sum_i cheb[k,i,j]*S[b,i,j] * xTheta[k,b,i,tc] )
// 64x128x8 tiles, 8x8 micro, 128 threads, double buffered. Prefetch uses an
// incremental (kpoly, i0) counter (no divisions) and an unpredicated fast path
// for interior tiles.
__global__ void __launch_bounds__(128) k_cheb(const float* __restrict__ cheb) {
    __shared__ __align__(16) float As[2][8][64];
    __shared__ __align__(16) float Bs[2][8][128];
    const int b = blockIdx.y;
    const int m0 = (blockIdx.x / 6) * 64;
    const int n0 = (blockIdx.x % 6) * 128;
    const int tid = threadIdx.x;
    const int tx = tid & 15, ty = tid >> 4;   // ty 0..7
    const float* Sb = g_S + (size_t)b*NNN;
    const bool mfull = (m0 + 64 <= NN);
    float acc[8][8];
    #pragma unroll
    for (int r = 0; r < 8; r++)
        #pragma unroll
        for (int q = 0; q < 8; q++) acc[r][q] = 0.f;

    // prologue kt=0 (k=0, i0=0)
    #pragma unroll
    for (int p = 0; p < 4; p++) {
        int e = tid + p*128;
        int kk = e >> 6, jl = e & 63;
        int i = kk, j = m0 + jl;
        float av = 0.f;
        if (i < NN && j < NN) { int id = i*NN + j; av = cheb[id]*Sb[id]; }
        As[0][kk][jl] = av;
    }
    #pragma unroll
    for (int p = 0; p < 8; p++) {
        int e = tid + p*128;
        int kk = e >> 7, cl = e & 127;
        Bs[0][kk][cl] = (kk < NN) ? g_xTheta[((size_t)b*NN + kk)*CTT + n0 + cl] : 0.f;
    }
    __syncthreads();
    const int NKT = 3*39;  // 117
    int nkp = 0, ni0 = 8;  // (kpoly, i0) of iteration kt+1
    for (int kt = 0; kt < NKT; kt++) {
        int cur = kt & 1;
        float ar[4], br[8];
        if (kt + 1 < NKT) {
            const float* Ck = cheb + (size_t)nkp*NNN;
            const float* Xk = g_xTheta + (size_t)(nkp*BB + b)*NN*CTT;
            const bool kfull = (ni0 + 8 <= NN);
            if (kfull & mfull) {
                // interior tile: no predicates
                #pragma unroll
                for (int p = 0; p < 4; p++) {
                    int e = tid + p*128;
                    int id = (ni0 + (e >> 6))*NN + m0 + (e & 63);
                    ar[p] = Ck[id]*Sb[id];
                }
                #pragma unroll
                for (int p = 0; p < 8; p++) {
                    int e = tid + p*128;
                    br[p] = Xk[(size_t)(ni0 + (e >> 7))*CTT + n0 + (e & 127)];
                }
            } else {
                #pragma unroll
                for (int p = 0; p < 4; p++) {
                    int e = tid + p*128;
                    int kk = e >> 6, jl = e & 63;
                    int i = ni0 + kk, j = m0 + jl;
                    float av = 0.f;
                    if (i < NN && j < NN) { int id = i*NN + j; av = Ck[id]*Sb[id]; }
                    ar[p] = av;
                }
                #pragma unroll
                for (int p = 0; p < 8; p++) {
                    int e = tid + p*128;
                    int kk = e >> 7, cl = e & 127;
                    int i = ni0 + kk;
                    br[p] = (i < NN) ? Xk[(size_t)i*CTT + n0 + cl] : 0.f;
                }
            }
            ni0 += 8;
            if (ni0 == 312) { ni0 = 0; nkp++; }
        }
        #pragma unroll
        for (int kk = 0; kk < 8; kk++) {
            float4 a0 = *(const float4*)&As[cur][kk][ty*8];
            float4 a1 = *(const float4*)&As[cur][kk][ty*8+4];
            float4 b0 = *(const float4*)&Bs[cur][kk][tx*8];
            float4 b1 = *(const float4*)&Bs[cur][kk][tx*8+4];
            float av[8] = {a0.x,a0.y,a0.z,a0.w,a1.x,a1.y,a1.z,a1.w};
            float bv[8] = {b0.x,b0.y,b0.z,b0.w,b1.x,b1.y,b1.z,b1.w};
            #pragma unroll
            for (int r = 0; r < 8; r++)
                #pragma unroll
                for (int q = 0; q < 8; q++) acc[r][q] += av[r]*bv[q];
        }
        if (kt + 1 < NKT) {
            int nxt = cur ^ 1;
            #pragma unroll
            for (int p = 0; p < 4; p++) {
                int e = tid + p*128;
                As[nxt][e>>6][e&63] = ar[p];
            }
            #pragma unroll
            for (int p = 0; p < 8; p++) {
                int e = tid + p*128;
                Bs[nxt][e>>7][e&127] = br[p];
            }
        }
        __syncthreads();
    }
    float* o = g_sg + (size_t)b*NN*CTT;
    #pragma unroll
    for (int r = 0; r < 8; r++) {
        int j = m0 + ty*8 + r;
        if (j >= NN) continue;
        float* orow = o + (size_t)j*CTT + n0 + tx*8;
        float4 v0 = make_float4(fmaxf(acc[r][0],0.f), fmaxf(acc[r][1],0.f),
                                fmaxf(acc[r][2],0.f), fmaxf(acc[r][3],0.f));
        float4 v1 = make_float4(fmaxf(acc[r][4],0.f), fmaxf(acc[r][5],0.f),
                                fmaxf(acc[r][6],0.f), fmaxf(acc[r][7],0.f));
        ((float4*)orow)[0] = v0;
        ((float4*)orow)[1] = v1;
    }
}

// fused: rconv + tconv + relu + LayerNorm. Block = 4 bn, 256 threads. (R6)
__global__ void __launch_bounds__(256) k_epi(
    const float* __restrict__ x, const float* __restrict__ tw, const float* __restrict__ tb,
    const float* __restrict__ rw, const float* __restrict__ rb,
    const float* __restrict__ gamma, const float* __restrict__ beta, float* __restrict__ out)
{
    extern __shared__ __align__(16) float sh[];
    float* wT  = sh;                 // 64*193
    float* wR  = wT + 64*193;        // 64*65
    float* xs  = wR + 64*65;         // 4*768
    float* sgs = xs + 4*768;         // 4*1024
    float* hs  = sgs + 4*1024;       // 4*832
    float* smu = hs + 4*832;         // 48
    float* srs = smu + 48;           // 48
    const int tid = threadIdx.x;
    const int bn_l = tid >> 6;
    const int co = tid & 63;
    const int bn0 = blockIdx.x * 4;

    for (int e = tid; e < 64*192; e += 256) wT[(e/192)*193 + (e%192)] = tw[e];
    for (int e = tid; e < 64*64;  e += 256) wR[(e>>6)*65 + (e&63)] = rw[e];
    for (int e = tid; e < 4*768;  e += 256) xs[e] = x[(size_t)bn0*768 + e];
    for (int e = tid; e < 4*1024; e += 256) sgs[e] = 0.f;
    __syncthreads();
    for (int e = tid; e < 4*768; e += 256) {
        int bl = e / 768, r = e % 768, t = r >> 6, c = r & 63;
        sgs[bl*1024 + c*16 + t + 1] = g_sg[(size_t)(bn0+bl)*768 + r];
    }
    __syncthreads();

    float acc[12];
    {
        float bias = tb[co] + rb[co];
        #pragma unroll
        for (int t = 0; t < 12; t++) acc[t] = bias;
    }
    const float* xrow = xs + bn_l*768;
    const float* wr = wR + co*65;
    #pragma unroll 4
    for (int f = 0; f < 64; f++) {
        float wf = wr[f];
        float4 x0 = *(const float4*)&xrow[f*12];
        float4 x1 = *(const float4*)&xrow[f*12+4];
        float4 x2 = *(const float4*)&xrow[f*12+8];
        acc[0] += wf*x0.x; acc[1] += wf*x0.y; acc[2]  += wf*x0.z; acc[3]  += wf*x0.w;
        acc[4] += wf*x1.x; acc[5] += wf*x1.y; acc[6]  += wf*x1.z; acc[7]  += wf*x1.w;
        acc[8] += wf*x2.x; acc[9] += wf*x2.y; acc[10] += wf*x2.z; acc[11] += wf*x2.w;
    }
    const float* sgr = sgs + bn_l*1024;
    const float* wt = wT + co*193;
    #pragma unroll 2
    for (int c = 0; c < 64; c++) {
        float w0 = wt[c*3], w1 = wt[c*3+1], w2 = wt[c*3+2];
        float4 s0 = *(const float4*)&sgr[c*16];
        float4 s1 = *(const float4*)&sgr[c*16+4];
        float4 s2 = *(const float4*)&sgr[c*16+8];
        float4 s3 = *(const float4*)&sgr[c*16+12];
        float sv[14] = {s0.x,s0.y,s0.z,s0.w, s1.x,s1.y,s1.z,s1.w,
                        s2.x,s2.y,s2.z,s2.w, s3.x,s3.y};
        #pragma unroll
        for (int t = 0; t < 12; t++)
            acc[t] += sv[t]*w0 + sv[t+1]*w1 + sv[t+2]*w2;
    }
    #pragma unroll
    for (int t = 0; t < 12; t++) {
        acc[t] = fmaxf(acc[t], 0.f);
        hs[bn_l*832 + co*13 + t] = acc[t];
    }
    __syncthreads();
    if (tid < 48) {
        int bl = tid / 12, t = tid % 12;
        const float* h = hs + bl*832;
        float m = 0.f;
        for (int q = 0; q < 64; q++) m += h[q*13 + t];
        m *= (1.f/64.f);
        float v = 0.f;
        for (int q = 0; q < 64; q++) { float d = h[q*13+t]-m; v += d*d; }
        v *= (1.f/64.f);
        smu[tid] = m;
        srs[tid] = rsqrtf(v + 1e-5f);
    }
    __syncthreads();
    float ga = gamma[co], be = beta[co];
    float* o = out + (((size_t)(bn0+bn_l))*64 + co)*12;
    #pragma unroll
    for (int t = 0; t < 12; t++)
        o[t] = (acc[t] - smu[bn_l*12+t])*srs[bn_l*12+t]*ga + be;
}

// ---------------- launch ----------------
extern "C" void kernel_launch(void* const* d_in, const int* in_sizes, int n_in,
                              void* d_out, int out_size) {
    const float* x    = (const float*)d_in[0];
    const float* W1   = (const float*)d_in[1];
    const float* W2   = (const float*)d_in[2];
    const float* W3   = (const float*)d_in[3];
    const float* b_s  = (const float*)d_in[4];
    const float* V_s  = (const float*)d_in[5];
    const float* U1   = (const float*)d_in[6];
    const float* U2   = (const float*)d_in[7];
    const float* U3   = (const float*)d_in[8];
    const float* b_e  = (const float*)d_in[9];
    const float* V_e  = (const float*)d_in[10];
    const float* cheb = (const float*)d_in[11];
    const float* Theta= (const float*)d_in[12];
    const float* tw   = (const float*)d_in[13];
    const float* tb   = (const float*)d_in[14];
    const float* rw   = (const float*)d_in[15];
    const float* rb   = (const float*)d_in[16];
    const float* gamma= (const float*)d_in[17];
    const float* beta = (const float*)d_in[18];
    float* out = (float*)d_out;

    k_tlhs_trhs<<<64 + 307, 768>>>(x, U1, U3);
    k_tlhs2<<<(BB*TT*NN+255)/256, 256>>>(U2);
    k_tattn<<<BB, 160>>>(b_e, V_e);
    k_xtat_fused<<<dim3(77, BB), 256>>>(x, W1, W3);
    k_slhs2<<<(BB*NN*TT+255)/256, 256>>>(W2);
    k_sprodsig<<<(BB*NN*NN + NNN + 255)/256, 256>>>(b_s, V_s);
    k_spre<<<dim3(154, 3), 256>>>();
    k_softS<<<dim3(BB, 5), 64>>>();
    k_xtheta<<<dim3(39, KK*BB), 192>>>(x, Theta);
    k_cheb<<<dim3(30, BB), 128>>>(cheb);   // 5 m-tiles(64) x 6 n-tiles(128)
    cudaFuncSetAttribute(k_epi, cudaFuncAttributeMaxDynamicSharedMemorySize, 112*1024);
    size_t epi_smem = (size_t)(64*193 + 64*65 + 4*768 + 4*1024 + 4*832 + 96)*sizeof(float);
    k_epi<<<MM/4, 256, epi_smem>>>(x, tw, tb, rw, rb, gamma, beta, out);
}